// round 3
// baseline (speedup 1.0000x reference)
#include <cuda_runtime.h>
#include <math.h>

#define D_MODEL 768
#define D_STATE 16
#define VOCAB   32000
#define D_INNER 1536
#define BATCH   2
#define SEQ     2048
#define ROWS    (BATCH*SEQ)     // 4096
#define LN_EPS  1e-5f

// ---------------- scratch (static device globals; no allocation) ----------------
__device__ float g_x [ROWS*D_MODEL];
__device__ float g_xp[ROWS*2*D_INNER];
__device__ float g_dt[ROWS*D_INNER];
__device__ float g_Bm[ROWS*D_STATE];
__device__ float g_Cm[ROWS*D_STATE];
__device__ float g_sg[ROWS*D_INNER];
__device__ float g_y2[ROWS*D_MODEL];
__device__ float g_xn[ROWS*D_MODEL];

// ---------------- embedding gather ----------------
__global__ void embed_kernel(const int* __restrict__ ids,
                             const float* __restrict__ emb,
                             float* __restrict__ x)
{
    int idx = blockIdx.x * 256 + threadIdx.x;
    if (idx >= ROWS*D_MODEL) return;
    int r = idx / D_MODEL, c = idx - r*D_MODEL;
    x[idx] = emb[(size_t)ids[r]*D_MODEL + c];
}

// ---------------- SGEMM: C[M,N] = A[M,K] * B[N,K]^T (all row-major, K contiguous)
// M % 128 == 0, N % 128 == 0, K % 16 == 0 (guaranteed by the shapes here).
__global__ __launch_bounds__(256) void sgemm_nt(
    const float* __restrict__ A, const float* __restrict__ B,
    float* __restrict__ C, int M, int N, int K)
{
    const int BM = 128, BN = 128, BK = 16;
    __shared__ float As[BK][BM+4];
    __shared__ float Bs[BK][BN+4];

    int tid = threadIdx.x;
    int tx = tid & 15, ty = tid >> 4;
    int bm = blockIdx.y * BM, bn = blockIdx.x * BN;

    const float* Ab = A + (size_t)bm * K;
    const float* Bb = B + (size_t)bn * K;

    float acc[8][8];
    #pragma unroll
    for (int i = 0; i < 8; ++i)
        #pragma unroll
        for (int j = 0; j < 8; ++j) acc[i][j] = 0.f;

    for (int k0 = 0; k0 < K; k0 += BK) {
        #pragma unroll
        for (int i = 0; i < 2; ++i) {
            int f   = tid + i*256;          // 0..511
            int row = f >> 2;               // 0..127
            int c4  = (f & 3) * 4;          // 0,4,8,12
            float4 va = *(const float4*)(Ab + (size_t)row*K + k0 + c4);
            As[c4+0][row] = va.x; As[c4+1][row] = va.y;
            As[c4+2][row] = va.z; As[c4+3][row] = va.w;
            float4 vb = *(const float4*)(Bb + (size_t)row*K + k0 + c4);
            Bs[c4+0][row] = vb.x; Bs[c4+1][row] = vb.y;
            Bs[c4+2][row] = vb.z; Bs[c4+3][row] = vb.w;
        }
        __syncthreads();

        #pragma unroll
        for (int kk = 0; kk < BK; ++kk) {
            float a[8], b[8];
            *(float4*)&a[0] = *(const float4*)&As[kk][ty*4];
            *(float4*)&a[4] = *(const float4*)&As[kk][64 + ty*4];
            *(float4*)&b[0] = *(const float4*)&Bs[kk][tx*4];
            *(float4*)&b[4] = *(const float4*)&Bs[kk][64 + tx*4];
            #pragma unroll
            for (int i = 0; i < 8; ++i)
                #pragma unroll
                for (int j = 0; j < 8; ++j)
                    acc[i][j] = fmaf(a[i], b[j], acc[i][j]);
        }
        __syncthreads();
    }

    #pragma unroll
    for (int i = 0; i < 8; ++i) {
        int mi = bm + ((i < 4) ? (ty*4 + i) : (64 + ty*4 + (i-4)));
        float4 v0 = make_float4(acc[i][0], acc[i][1], acc[i][2], acc[i][3]);
        float4 v1 = make_float4(acc[i][4], acc[i][5], acc[i][6], acc[i][7]);
        *(float4*)&C[(size_t)mi*N + bn + tx*4]      = v0;
        *(float4*)&C[(size_t)mi*N + bn + 64 + tx*4] = v1;
    }
}

// ---------------- dt activation: softplus(dt + b_dt + dt_bias) clipped to [0,1]
__global__ void dt_act_kernel(float* __restrict__ dt,
                              const float* __restrict__ bd,
                              const float* __restrict__ dtb)
{
    int idx = blockIdx.x * 256 + threadIdx.x;
    if (idx >= ROWS*D_INNER) return;
    int d = idx % D_INNER;
    float v = dt[idx] + bd[d] + dtb[d];
    float sp = (v > 20.f) ? v : log1pf(expf(v));
    dt[idx] = fminf(fmaxf(sp, 0.f), 1.f);
}

// ---------------- B/C projection: N=16 each, fused (reuses x row from smem)
__global__ __launch_bounds__(256) void bc_kernel(
    const float* __restrict__ x, const float* __restrict__ WB,
    const float* __restrict__ WC, float* __restrict__ Bm, float* __restrict__ Cm)
{
    int r = blockIdx.x;
    __shared__ float xs[D_MODEL];
    __shared__ float part[32][9];
    int tid = threadIdx.x;
    for (int i = tid; i < D_MODEL; i += 256) xs[i] = x[(size_t)r*D_MODEL + i];
    __syncthreads();

    int o = tid & 31;        // output 0..31 (16 B + 16 C)
    int chunk = tid >> 5;    // 0..7 (96 elems each)
    const float* w = (o < 16) ? (WB + (size_t)o*D_MODEL)
                              : (WC + (size_t)(o-16)*D_MODEL);
    float s = 0.f;
    int k0 = chunk * 96;
    #pragma unroll 4
    for (int k = k0; k < k0 + 96; ++k) s = fmaf(xs[k], w[k], s);
    part[o][chunk] = s;
    __syncthreads();
    if (tid < 32) {
        float t = 0.f;
        #pragma unroll
        for (int c = 0; c < 8; ++c) t += part[tid][c];
        if (tid < 16) Bm[(size_t)r*16 + tid]        = t;
        else          Cm[(size_t)r*16 + (tid-16)]   = t;
    }
}

// ---------------- SSM scan: 8 threads/channel, 2 states/thread, fused gate
__global__ __launch_bounds__(128) void scan_kernel(
    const float* __restrict__ xp,  // [ROWS, 2*D_INNER]
    const float* __restrict__ dt,  // [ROWS, D_INNER]
    const float* __restrict__ Bm,  // [ROWS, 16]
    const float* __restrict__ Cm,  // [ROWS, 16]
    const float* __restrict__ A,   // [D_INNER, 16]
    const float* __restrict__ Dp,  // [D_INNER]
    float* __restrict__ out)       // [ROWS, D_INNER] gated ssm output
{
    const int TPC = 8;
    int lane_c = threadIdx.x & (TPC-1);
    int ch = blockIdx.x * (128/TPC) + (threadIdx.x >> 3);   // 0..3071
    int b = ch / D_INNER, d = ch - b*D_INNER;
    int s0 = lane_c * 2;

    float a0 = A[(size_t)d*D_STATE + s0];
    float a1 = A[(size_t)d*D_STATE + s0 + 1];
    float Dd = Dp[d];
    float h0 = 0.f, h1 = 0.f;

    const int rowbase = b * SEQ;
    for (int t = 0; t < SEQ; ++t) {
        int r = rowbase + t;
        float u   = xp[(size_t)r*(2*D_INNER) + d];
        float dtc = dt[(size_t)r*D_INNER + d];
        float2 Bv = *(const float2*)&Bm[(size_t)r*D_STATE + s0];
        float2 Cv = *(const float2*)&Cm[(size_t)r*D_STATE + s0];

        float adt = (a0 * dtc) * 0.1f;          // grouping mirrors (A*dtc)*0.1
        float adt1 = (a1 * dtc) * 0.1f;
        float bu0 = (Bv.x * u) * 0.1f;          // (B*u)*0.1
        float bu1 = (Bv.y * u) * 0.1f;
        h0 = h0 * (1.0f + adt)  + bu0;
        h1 = h1 * (1.0f + adt1) + bu1;

        float y = fmaf(h0, Cv.x, h1 * Cv.y);
        y += __shfl_xor_sync(0xffffffffu, y, 1);
        y += __shfl_xor_sync(0xffffffffu, y, 2);
        y += __shfl_xor_sync(0xffffffffu, y, 4);

        if (lane_c == 0) {
            float gin = xp[(size_t)r*(2*D_INNER) + D_INNER + d];
            float gate = 1.0f / (1.0f + expf(-gin));
            out[(size_t)r*D_INNER + d] = (y + Dd * u) * gate;
        }
    }
}

// ---------------- block reduce helper ----------------
__device__ __forceinline__ float block_sum_256(float v, float* red) {
    #pragma unroll
    for (int m = 16; m > 0; m >>= 1) v += __shfl_xor_sync(0xffffffffu, v, m);
    int w = threadIdx.x >> 5;
    if ((threadIdx.x & 31) == 0) red[w] = v;
    __syncthreads();
    float s = 0.f;
    if (threadIdx.x == 0) {
        #pragma unroll
        for (int i = 0; i < 8; ++i) s += red[i];
        red[0] = s;
    }
    __syncthreads();
    s = red[0];
    __syncthreads();
    return s;
}

// ---------------- x = x + LN(x + y2) * g + b  (one block per row, 768 wide)
__global__ __launch_bounds__(256) void ln_residual_kernel(
    float* __restrict__ x, const float* __restrict__ y2,
    const float* __restrict__ g, const float* __restrict__ b)
{
    __shared__ float red[8];
    int r = blockIdx.x, tid = threadIdx.x;
    size_t base = (size_t)r * D_MODEL;
    float v[3], xo[3];
    #pragma unroll
    for (int i = 0; i < 3; ++i) {
        int c = i*256 + tid;
        xo[i] = x[base + c];
        v[i]  = xo[i] + y2[base + c];
    }
    float mu = block_sum_256(v[0]+v[1]+v[2], red) * (1.0f/D_MODEL);
    float q = 0.f;
    #pragma unroll
    for (int i = 0; i < 3; ++i) { float dv = v[i]-mu; q = fmaf(dv, dv, q); }
    float var = block_sum_256(q, red) * (1.0f/D_MODEL);
    float rstd = rsqrtf(var + LN_EPS);
    #pragma unroll
    for (int i = 0; i < 3; ++i) {
        int c = i*256 + tid;
        x[base + c] = xo[i] + (v[i]-mu)*rstd*g[c] + b[c];
    }
}

// ---------------- xn = LN(x) * fin_g + fin_b ----------------
__global__ __launch_bounds__(256) void final_ln_kernel(
    const float* __restrict__ x, float* __restrict__ xn,
    const float* __restrict__ g, const float* __restrict__ b)
{
    __shared__ float red[8];
    int r = blockIdx.x, tid = threadIdx.x;
    size_t base = (size_t)r * D_MODEL;
    float v[3];
    #pragma unroll
    for (int i = 0; i < 3; ++i) v[i] = x[base + i*256 + tid];
    float mu = block_sum_256(v[0]+v[1]+v[2], red) * (1.0f/D_MODEL);
    float q = 0.f;
    #pragma unroll
    for (int i = 0; i < 3; ++i) { float dv = v[i]-mu; q = fmaf(dv, dv, q); }
    float var = block_sum_256(q, red) * (1.0f/D_MODEL);
    float rstd = rsqrtf(var + LN_EPS);
    #pragma unroll
    for (int i = 0; i < 3; ++i) {
        int c = i*256 + tid;
        xn[base + c] = (v[i]-mu)*rstd*g[c] + b[c];
    }
}

// ---------------- launch ----------------
extern "C" void kernel_launch(void* const* d_in, const int* in_sizes, int n_in,
                              void* d_out, int out_size)
{
    const int*   ids    = (const int*)  d_in[0];
    const float* emb    = (const float*)d_in[1];
    const float* W_in   = (const float*)d_in[2];
    const float* W_dt   = (const float*)d_in[3];
    const float* b_dt   = (const float*)d_in[4];
    const float* dt_b   = (const float*)d_in[5];
    const float* W_B    = (const float*)d_in[6];
    const float* W_C    = (const float*)d_in[7];
    const float* A      = (const float*)d_in[8];
    const float* Dp     = (const float*)d_in[9];
    const float* W_out  = (const float*)d_in[10];
    const float* ln_g   = (const float*)d_in[11];
    const float* ln_b   = (const float*)d_in[12];
    const float* fin_g  = (const float*)d_in[13];
    const float* fin_b  = (const float*)d_in[14];
    float* out = (float*)d_out;

    float *x, *xp, *dt, *Bm, *Cm, *sg, *y2, *xn;
    cudaGetSymbolAddress((void**)&x,  g_x);
    cudaGetSymbolAddress((void**)&xp, g_xp);
    cudaGetSymbolAddress((void**)&dt, g_dt);
    cudaGetSymbolAddress((void**)&Bm, g_Bm);
    cudaGetSymbolAddress((void**)&Cm, g_Cm);
    cudaGetSymbolAddress((void**)&sg, g_sg);
    cudaGetSymbolAddress((void**)&y2, g_y2);
    cudaGetSymbolAddress((void**)&xn, g_xn);

    embed_kernel<<<(ROWS*D_MODEL + 255)/256, 256>>>(ids, emb, x);

    for (int l = 0; l < 2; ++l) {
        const float* Wi  = W_in  + (size_t)l * (2*D_INNER) * D_MODEL;
        const float* Wd  = W_dt  + (size_t)l * D_INNER * D_MODEL;
        const float* bd  = b_dt  + (size_t)l * D_INNER;
        const float* dtb = dt_b  + (size_t)l * D_INNER;
        const float* WBl = W_B   + (size_t)l * D_STATE * D_MODEL;
        const float* WCl = W_C   + (size_t)l * D_STATE * D_MODEL;
        const float* Al  = A     + (size_t)l * D_INNER * D_STATE;
        const float* Dl  = Dp    + (size_t)l * D_INNER;
        const float* Wo  = W_out + (size_t)l * D_MODEL * D_INNER;
        const float* lg  = ln_g  + (size_t)l * D_MODEL;
        const float* lb  = ln_b  + (size_t)l * D_MODEL;

        sgemm_nt<<<dim3((2*D_INNER)/128, ROWS/128), 256>>>(x, Wi, xp, ROWS, 2*D_INNER, D_MODEL);
        sgemm_nt<<<dim3(D_INNER/128,     ROWS/128), 256>>>(x, Wd, dt, ROWS, D_INNER, D_MODEL);
        dt_act_kernel<<<(ROWS*D_INNER + 255)/256, 256>>>(dt, bd, dtb);
        bc_kernel<<<ROWS, 256>>>(x, WBl, WCl, Bm, Cm);
        scan_kernel<<<(BATCH*D_INNER)/16, 128>>>(xp, dt, Bm, Cm, Al, Dl, sg);
        sgemm_nt<<<dim3(D_MODEL/128, ROWS/128), 256>>>(sg, Wo, y2, ROWS, D_MODEL, D_INNER);
        ln_residual_kernel<<<ROWS, 256>>>(x, y2, lg, lb);
    }

    final_ln_kernel<<<ROWS, 256>>>(x, xn, fin_g, fin_b);
    sgemm_nt<<<dim3(VOCAB/128, ROWS/128), 256>>>(xn, emb, out, ROWS, VOCAB, D_MODEL);
}

// round 4
// speedup vs baseline: 1.4144x; 1.4144x over previous
#include <cuda_runtime.h>
#include <cuda_bf16.h>
#include <math.h>
#include <stdint.h>

#define D_MODEL 768
#define D_STATE 16
#define VOCAB   32000
#define D_INNER 1536
#define BATCH   2
#define SEQ     2048
#define ROWS    (BATCH*SEQ)     // 4096
#define LN_EPS  1e-5f
#define NL      2

// ---------------- scratch (static device globals; no allocation) ----------------
__device__ float g_x [ROWS*D_MODEL];
__device__ float g_xp[ROWS*2*D_INNER];
__device__ float g_dt[ROWS*D_INNER];
__device__ float g_Bm[ROWS*D_STATE];
__device__ float g_Cm[ROWS*D_STATE];
__device__ float g_y2[ROWS*D_MODEL];

// bf16 hi/lo split buffers
__device__ __nv_bfloat16 g_emb_h[VOCAB*D_MODEL], g_emb_l[VOCAB*D_MODEL];
__device__ __nv_bfloat16 g_Win_h[NL*2*D_INNER*D_MODEL], g_Win_l[NL*2*D_INNER*D_MODEL];
__device__ __nv_bfloat16 g_Wdt_h[NL*D_INNER*D_MODEL],   g_Wdt_l[NL*D_INNER*D_MODEL];
__device__ __nv_bfloat16 g_Wout_h[NL*D_MODEL*D_INNER],  g_Wout_l[NL*D_MODEL*D_INNER];
__device__ __nv_bfloat16 g_xh[ROWS*D_MODEL],  g_xl[ROWS*D_MODEL];
__device__ __nv_bfloat16 g_sgh[ROWS*D_INNER], g_sgl[ROWS*D_INNER];
__device__ __nv_bfloat16 g_xnh[ROWS*D_MODEL], g_xnl[ROWS*D_MODEL];

__device__ __forceinline__ void split2(float v, __nv_bfloat16& h, __nv_bfloat16& l) {
    h = __float2bfloat16(v);
    l = __float2bfloat16(v - __bfloat162float(h));
}

// ---------------- fp32 -> (hi,lo) bf16 split ----------------
__global__ void split_kernel(const float* __restrict__ w,
                             __nv_bfloat16* __restrict__ h,
                             __nv_bfloat16* __restrict__ l, int n)
{
    int i = blockIdx.x * 256 + threadIdx.x;
    if (i >= n) return;
    split2(w[i], h[i], l[i]);
}

// ---------------- embedding gather (+ split) ----------------
__global__ void embed_kernel(const int* __restrict__ ids,
                             const float* __restrict__ emb,
                             float* __restrict__ x,
                             __nv_bfloat16* __restrict__ xh,
                             __nv_bfloat16* __restrict__ xl)
{
    int idx = blockIdx.x * 256 + threadIdx.x;
    if (idx >= ROWS*D_MODEL) return;
    int r = idx / D_MODEL, c = idx - r*D_MODEL;
    float v = emb[(size_t)ids[r]*D_MODEL + c];
    x[idx] = v;
    split2(v, xh[idx], xl[idx]);
}

// ================= bf16x3 tensor-core GEMM =================
// C[M,N] = A[M,K] * B[N,K]^T  where A ~= Ah+Al, B ~= Bh+Bl (bf16 hi/lo).
// Block tile 128x128, BK=32, 8 warps (2x4), warp tile 64x32, mma m16n8k16.
// cp.async double-buffered smem, ldmatrix fragment loads, 3 mma passes per tile.

__device__ __forceinline__ void cp16(uint32_t s, const void* g) {
    asm volatile("cp.async.cg.shared.global [%0], [%1], 16;" :: "r"(s), "l"(g));
}
__device__ __forceinline__ void cp_commit() {
    asm volatile("cp.async.commit_group;");
}
template<int N> __device__ __forceinline__ void cp_wait() {
    asm volatile("cp.async.wait_group %0;" :: "n"(N));
}
__device__ __forceinline__ void ldm_x4(uint32_t (&r)[4], uint32_t addr) {
    asm volatile("ldmatrix.sync.aligned.m8n8.x4.shared.b16 {%0,%1,%2,%3}, [%4];"
        : "=r"(r[0]), "=r"(r[1]), "=r"(r[2]), "=r"(r[3]) : "r"(addr));
}
__device__ __forceinline__ void mma_bf16(float (&c)[4], const uint32_t (&a)[4],
                                         const uint32_t* b) {
    asm volatile(
        "mma.sync.aligned.m16n8k16.row.col.f32.bf16.bf16.f32 "
        "{%0,%1,%2,%3}, {%4,%5,%6,%7}, {%8,%9}, {%0,%1,%2,%3};"
        : "+f"(c[0]), "+f"(c[1]), "+f"(c[2]), "+f"(c[3])
        : "r"(a[0]), "r"(a[1]), "r"(a[2]), "r"(a[3]), "r"(b[0]), "r"(b[1]));
}

#define GPITCH 40                       // bf16 elems per smem row (32 data + 8 pad)
#define GTILE_B (128*GPITCH*2)          // bytes per tile (10240)
#define GSTAGE_B (4*GTILE_B)            // 4 tiles per stage (Ah,Al,Bh,Bl)
#define GSMEM_B (2*GSTAGE_B)            // 81920 bytes

__global__ __launch_bounds__(256, 1) void gemm_bf16x3(
    const __nv_bfloat16* __restrict__ Ah, const __nv_bfloat16* __restrict__ Al,
    const __nv_bfloat16* __restrict__ Bh, const __nv_bfloat16* __restrict__ Bl,
    float* __restrict__ C, int M, int N, int K)
{
    extern __shared__ __nv_bfloat16 sm[];
    int tid = threadIdx.x, lane = tid & 31, warp = tid >> 5;
    int wm = warp >> 2, wn = warp & 3;               // 2 x 4 warp grid
    int bm = blockIdx.y * 128, bn = blockIdx.x * 128;
    uint32_t sb = (uint32_t)__cvta_generic_to_shared(sm);

    float acc[4][4][4];
    #pragma unroll
    for (int i = 0; i < 4; ++i)
        #pragma unroll
        for (int j = 0; j < 4; ++j)
            #pragma unroll
            for (int k = 0; k < 4; ++k) acc[i][j][k] = 0.f;

    auto issue = [&](int stg, int k0) {
        uint32_t base = sb + stg * GSTAGE_B;
        #pragma unroll
        for (int i = 0; i < 2; ++i) {
            int chunk = tid + i * 256;               // 0..511
            int row = chunk >> 2, c16 = chunk & 3;   // 128 rows x 4 chunks of 16B
            uint32_t so = (uint32_t)(row * GPITCH + c16 * 8) * 2;
            size_t ga = (size_t)(bm + row) * K + k0 + c16 * 8;
            size_t gb = (size_t)(bn + row) * K + k0 + c16 * 8;
            cp16(base + so,              Ah + ga);
            cp16(base +   GTILE_B + so,  Al + ga);
            cp16(base + 2*GTILE_B + so,  Bh + gb);
            cp16(base + 3*GTILE_B + so,  Bl + gb);
        }
    };

    int nit = K / 32;
    issue(0, 0);
    cp_commit();

    // per-lane ldmatrix address components (rows within tile, cols in elems)
    int a_r = wm * 64 + (lane & 7) + ((lane >> 3) & 1) * 8;
    int a_c = (lane >> 4) * 8;
    int b_r = wn * 32 + (lane & 7) + ((lane >> 4) & 1) * 8;
    int b_c = ((lane >> 3) & 1) * 8;

    for (int it = 0; it < nit; ++it) {
        int cur = it & 1;
        if (it + 1 < nit) { issue((it + 1) & 1, (it + 1) * 32); cp_commit(); cp_wait<1>(); }
        else              { cp_wait<0>(); }
        __syncthreads();

        uint32_t base = sb + cur * GSTAGE_B;
        #pragma unroll
        for (int ks = 0; ks < 2; ++ks) {
            uint32_t ah[4][4], al[4][4], bh[4][2], bl[4][2];
            #pragma unroll
            for (int mt = 0; mt < 4; ++mt) {
                uint32_t off = (uint32_t)((a_r + mt * 16) * GPITCH + a_c + ks * 16) * 2;
                ldm_x4(ah[mt], base + off);
                ldm_x4(al[mt], base + GTILE_B + off);
            }
            #pragma unroll
            for (int g = 0; g < 2; ++g) {
                uint32_t off = (uint32_t)((b_r + g * 16) * GPITCH + b_c + ks * 16) * 2;
                uint32_t t[4];
                ldm_x4(t, base + 2*GTILE_B + off);
                bh[g*2][0] = t[0]; bh[g*2][1] = t[1];
                bh[g*2+1][0] = t[2]; bh[g*2+1][1] = t[3];
                ldm_x4(t, base + 3*GTILE_B + off);
                bl[g*2][0] = t[0]; bl[g*2][1] = t[1];
                bl[g*2+1][0] = t[2]; bl[g*2+1][1] = t[3];
            }
            #pragma unroll
            for (int mt = 0; mt < 4; ++mt)
                #pragma unroll
                for (int nt = 0; nt < 4; ++nt) {
                    mma_bf16(acc[mt][nt], ah[mt], bh[nt]);
                    mma_bf16(acc[mt][nt], ah[mt], bl[nt]);
                    mma_bf16(acc[mt][nt], al[mt], bh[nt]);
                }
        }
        __syncthreads();
    }

    // epilogue
    #pragma unroll
    for (int mt = 0; mt < 4; ++mt) {
        int r = bm + wm * 64 + mt * 16 + (lane >> 2);
        #pragma unroll
        for (int nt = 0; nt < 4; ++nt) {
            int c = bn + wn * 32 + nt * 8 + (lane & 3) * 2;
            *(float2*)&C[(size_t)r * N + c]       = make_float2(acc[mt][nt][0], acc[mt][nt][1]);
            *(float2*)&C[(size_t)(r + 8) * N + c] = make_float2(acc[mt][nt][2], acc[mt][nt][3]);
        }
    }
}

// ---------------- dt activation: softplus(dt + b_dt + dt_bias) clipped to [0,1]
__global__ void dt_act_kernel(float* __restrict__ dt,
                              const float* __restrict__ bd,
                              const float* __restrict__ dtb)
{
    int idx = blockIdx.x * 256 + threadIdx.x;
    if (idx >= ROWS*D_INNER) return;
    int d = idx % D_INNER;
    float v = dt[idx] + bd[d] + dtb[d];
    float sp = (v > 20.f) ? v : log1pf(expf(v));
    dt[idx] = fminf(fmaxf(sp, 0.f), 1.f);
}

// ---------------- B/C projection: N=16 each, fused (reuses x row from smem)
__global__ __launch_bounds__(256) void bc_kernel(
    const float* __restrict__ x, const float* __restrict__ WB,
    const float* __restrict__ WC, float* __restrict__ Bm, float* __restrict__ Cm)
{
    int r = blockIdx.x;
    __shared__ float xs[D_MODEL];
    __shared__ float part[32][9];
    int tid = threadIdx.x;
    for (int i = tid; i < D_MODEL; i += 256) xs[i] = x[(size_t)r*D_MODEL + i];
    __syncthreads();

    int o = tid & 31;
    int chunk = tid >> 5;
    const float* w = (o < 16) ? (WB + (size_t)o*D_MODEL)
                              : (WC + (size_t)(o-16)*D_MODEL);
    float s = 0.f;
    int k0 = chunk * 96;
    #pragma unroll 4
    for (int k = k0; k < k0 + 96; ++k) s = fmaf(xs[k], w[k], s);
    part[o][chunk] = s;
    __syncthreads();
    if (tid < 32) {
        float t = 0.f;
        #pragma unroll
        for (int c = 0; c < 8; ++c) t += part[tid][c];
        if (tid < 16) Bm[(size_t)r*16 + tid]      = t;
        else          Cm[(size_t)r*16 + (tid-16)] = t;
    }
}

// ---------------- SSM scan: 8 threads/channel, 2 states/thread, fused gate+split
__global__ __launch_bounds__(128) void scan_kernel(
    const float* __restrict__ xp,  // [ROWS, 2*D_INNER]
    const float* __restrict__ dt,  // [ROWS, D_INNER]
    const float* __restrict__ Bm,  // [ROWS, 16]
    const float* __restrict__ Cm,  // [ROWS, 16]
    const float* __restrict__ A,   // [D_INNER, 16]
    const float* __restrict__ Dp,  // [D_INNER]
    __nv_bfloat16* __restrict__ outh,
    __nv_bfloat16* __restrict__ outl)
{
    const int TPC = 8;
    int lane_c = threadIdx.x & (TPC-1);
    int ch = blockIdx.x * (128/TPC) + (threadIdx.x >> 3);   // 0..3071
    int b = ch / D_INNER, d = ch - b*D_INNER;
    int s0 = lane_c * 2;

    float a0 = A[(size_t)d*D_STATE + s0];
    float a1 = A[(size_t)d*D_STATE + s0 + 1];
    float Dd = Dp[d];
    float h0 = 0.f, h1 = 0.f;

    const int rowbase = b * SEQ;
    for (int t = 0; t < SEQ; ++t) {
        int r = rowbase + t;
        float u   = xp[(size_t)r*(2*D_INNER) + d];
        float dtc = dt[(size_t)r*D_INNER + d];
        float2 Bv = *(const float2*)&Bm[(size_t)r*D_STATE + s0];
        float2 Cv = *(const float2*)&Cm[(size_t)r*D_STATE + s0];

        float adt0 = (a0 * dtc) * 0.1f;
        float adt1 = (a1 * dtc) * 0.1f;
        float bu0  = (Bv.x * u) * 0.1f;
        float bu1  = (Bv.y * u) * 0.1f;
        h0 = h0 * (1.0f + adt0) + bu0;
        h1 = h1 * (1.0f + adt1) + bu1;

        float y = fmaf(h0, Cv.x, h1 * Cv.y);
        y += __shfl_xor_sync(0xffffffffu, y, 1);
        y += __shfl_xor_sync(0xffffffffu, y, 2);
        y += __shfl_xor_sync(0xffffffffu, y, 4);

        if (lane_c == 0) {
            float gin = xp[(size_t)r*(2*D_INNER) + D_INNER + d];
            float gate = 1.0f / (1.0f + expf(-gin));
            float val = (y + Dd * u) * gate;
            size_t idx = (size_t)r*D_INNER + d;
            split2(val, outh[idx], outl[idx]);
        }
    }
}

// ---------------- block reduce helper ----------------
__device__ __forceinline__ float block_sum_256(float v, float* red) {
    #pragma unroll
    for (int m = 16; m > 0; m >>= 1) v += __shfl_xor_sync(0xffffffffu, v, m);
    int w = threadIdx.x >> 5;
    if ((threadIdx.x & 31) == 0) red[w] = v;
    __syncthreads();
    float s = 0.f;
    if (threadIdx.x == 0) {
        #pragma unroll
        for (int i = 0; i < 8; ++i) s += red[i];
        red[0] = s;
    }
    __syncthreads();
    s = red[0];
    __syncthreads();
    return s;
}

// ---------------- x = x + LN(x + y2) * g + b, plus hi/lo split of new x
__global__ __launch_bounds__(256) void ln_residual_kernel(
    float* __restrict__ x, const float* __restrict__ y2,
    const float* __restrict__ g, const float* __restrict__ b,
    __nv_bfloat16* __restrict__ xh, __nv_bfloat16* __restrict__ xl)
{
    __shared__ float red[8];
    int r = blockIdx.x, tid = threadIdx.x;
    size_t base = (size_t)r * D_MODEL;
    float v[3], xo[3];
    #pragma unroll
    for (int i = 0; i < 3; ++i) {
        int c = i*256 + tid;
        xo[i] = x[base + c];
        v[i]  = xo[i] + y2[base + c];
    }
    float mu = block_sum_256(v[0]+v[1]+v[2], red) * (1.0f/D_MODEL);
    float q = 0.f;
    #pragma unroll
    for (int i = 0; i < 3; ++i) { float dv = v[i]-mu; q = fmaf(dv, dv, q); }
    float var = block_sum_256(q, red) * (1.0f/D_MODEL);
    float rstd = rsqrtf(var + LN_EPS);
    #pragma unroll
    for (int i = 0; i < 3; ++i) {
        int c = i*256 + tid;
        float nv = xo[i] + (v[i]-mu)*rstd*g[c] + b[c];
        x[base + c] = nv;
        split2(nv, xh[base + c], xl[base + c]);
    }
}

// ---------------- xn = LN(x) * fin_g + fin_b, written as hi/lo bf16
__global__ __launch_bounds__(256) void final_ln_kernel(
    const float* __restrict__ x,
    __nv_bfloat16* __restrict__ xnh, __nv_bfloat16* __restrict__ xnl,
    const float* __restrict__ g, const float* __restrict__ b)
{
    __shared__ float red[8];
    int r = blockIdx.x, tid = threadIdx.x;
    size_t base = (size_t)r * D_MODEL;
    float v[3];
    #pragma unroll
    for (int i = 0; i < 3; ++i) v[i] = x[base + i*256 + tid];
    float mu = block_sum_256(v[0]+v[1]+v[2], red) * (1.0f/D_MODEL);
    float q = 0.f;
    #pragma unroll
    for (int i = 0; i < 3; ++i) { float dv = v[i]-mu; q = fmaf(dv, dv, q); }
    float var = block_sum_256(q, red) * (1.0f/D_MODEL);
    float rstd = rsqrtf(var + LN_EPS);
    #pragma unroll
    for (int i = 0; i < 3; ++i) {
        int c = i*256 + tid;
        float nv = (v[i]-mu)*rstd*g[c] + b[c];
        split2(nv, xnh[base + c], xnl[base + c]);
    }
}

// ---------------- launch ----------------
extern "C" void kernel_launch(void* const* d_in, const int* in_sizes, int n_in,
                              void* d_out, int out_size)
{
    const int*   ids    = (const int*)  d_in[0];
    const float* emb    = (const float*)d_in[1];
    const float* W_in   = (const float*)d_in[2];
    const float* W_dt   = (const float*)d_in[3];
    const float* b_dt   = (const float*)d_in[4];
    const float* dt_b   = (const float*)d_in[5];
    const float* W_B    = (const float*)d_in[6];
    const float* W_C    = (const float*)d_in[7];
    const float* A      = (const float*)d_in[8];
    const float* Dp     = (const float*)d_in[9];
    const float* W_out  = (const float*)d_in[10];
    const float* ln_g   = (const float*)d_in[11];
    const float* ln_b   = (const float*)d_in[12];
    const float* fin_g  = (const float*)d_in[13];
    const float* fin_b  = (const float*)d_in[14];
    float* out = (float*)d_out;

    float *x, *xp, *dt, *Bm, *Cm, *y2;
    cudaGetSymbolAddress((void**)&x,  g_x);
    cudaGetSymbolAddress((void**)&xp, g_xp);
    cudaGetSymbolAddress((void**)&dt, g_dt);
    cudaGetSymbolAddress((void**)&Bm, g_Bm);
    cudaGetSymbolAddress((void**)&Cm, g_Cm);
    cudaGetSymbolAddress((void**)&y2, g_y2);

    __nv_bfloat16 *embh, *embl, *winh, *winl, *wdth, *wdtl, *wouth, *woutl;
    __nv_bfloat16 *xh, *xl, *sgh, *sgl, *xnh, *xnl;
    cudaGetSymbolAddress((void**)&embh, g_emb_h);  cudaGetSymbolAddress((void**)&embl, g_emb_l);
    cudaGetSymbolAddress((void**)&winh, g_Win_h);  cudaGetSymbolAddress((void**)&winl, g_Win_l);
    cudaGetSymbolAddress((void**)&wdth, g_Wdt_h);  cudaGetSymbolAddress((void**)&wdtl, g_Wdt_l);
    cudaGetSymbolAddress((void**)&wouth, g_Wout_h); cudaGetSymbolAddress((void**)&woutl, g_Wout_l);
    cudaGetSymbolAddress((void**)&xh, g_xh);   cudaGetSymbolAddress((void**)&xl, g_xl);
    cudaGetSymbolAddress((void**)&sgh, g_sgh); cudaGetSymbolAddress((void**)&sgl, g_sgl);
    cudaGetSymbolAddress((void**)&xnh, g_xnh); cudaGetSymbolAddress((void**)&xnl, g_xnl);

    cudaFuncSetAttribute(gemm_bf16x3, cudaFuncAttributeMaxDynamicSharedMemorySize, GSMEM_B);

    // split weights + embedding into bf16 hi/lo
    {
        int n;
        n = VOCAB*D_MODEL;            split_kernel<<<(n+255)/256,256>>>(emb,   embh, embl, n);
        n = NL*2*D_INNER*D_MODEL;     split_kernel<<<(n+255)/256,256>>>(W_in,  winh, winl, n);
        n = NL*D_INNER*D_MODEL;       split_kernel<<<(n+255)/256,256>>>(W_dt,  wdth, wdtl, n);
        n = NL*D_MODEL*D_INNER;       split_kernel<<<(n+255)/256,256>>>(W_out, wouth, woutl, n);
    }

    embed_kernel<<<(ROWS*D_MODEL + 255)/256, 256>>>(ids, emb, x, xh, xl);

    for (int l = 0; l < NL; ++l) {
        size_t oWin = (size_t)l * (2*D_INNER) * D_MODEL;
        size_t oWdt = (size_t)l * D_INNER * D_MODEL;
        size_t oWo  = (size_t)l * D_MODEL * D_INNER;
        const float* bd  = b_dt + (size_t)l * D_INNER;
        const float* dtb = dt_b + (size_t)l * D_INNER;
        const float* WBl = W_B  + (size_t)l * D_STATE * D_MODEL;
        const float* WCl = W_C  + (size_t)l * D_STATE * D_MODEL;
        const float* Al  = A    + (size_t)l * D_INNER * D_STATE;
        const float* Dl  = Dp   + (size_t)l * D_INNER;
        const float* lg  = ln_g + (size_t)l * D_MODEL;
        const float* lb  = ln_b + (size_t)l * D_MODEL;

        gemm_bf16x3<<<dim3((2*D_INNER)/128, ROWS/128), 256, GSMEM_B>>>(
            xh, xl, winh + oWin, winl + oWin, xp, ROWS, 2*D_INNER, D_MODEL);
        gemm_bf16x3<<<dim3(D_INNER/128, ROWS/128), 256, GSMEM_B>>>(
            xh, xl, wdth + oWdt, wdtl + oWdt, dt, ROWS, D_INNER, D_MODEL);
        dt_act_kernel<<<(ROWS*D_INNER + 255)/256, 256>>>(dt, bd, dtb);
        bc_kernel<<<ROWS, 256>>>(x, WBl, WCl, Bm, Cm);
        scan_kernel<<<(BATCH*D_INNER)/16, 128>>>(xp, dt, Bm, Cm, Al, Dl, sgh, sgl);
        gemm_bf16x3<<<dim3(D_MODEL/128, ROWS/128), 256, GSMEM_B>>>(
            sgh, sgl, wouth + oWo, woutl + oWo, y2, ROWS, D_MODEL, D_INNER);
        ln_residual_kernel<<<ROWS, 256>>>(x, y2, lg, lb, xh, xl);
    }

    final_ln_kernel<<<ROWS, 256>>>(x, xnh, xnl, fin_g, fin_b);
    gemm_bf16x3<<<dim3(VOCAB/128, ROWS/128), 256, GSMEM_B>>>(
        xnh, xnl, embh, embl, out, ROWS, VOCAB, D_MODEL);
}

// round 9
// speedup vs baseline: 1.4229x; 1.0061x over previous
#include <cuda_runtime.h>
#include <cuda_bf16.h>
#include <math.h>
#include <stdint.h>

#define D_MODEL 768
#define D_STATE 16
#define VOCAB   32000
#define D_INNER 1536
#define BATCH   2
#define SEQ     2048
#define ROWS    (BATCH*SEQ)     // 4096
#define LN_EPS  1e-5f
#define NL      2

// ---------------- scratch (static device globals; no allocation) ----------------
__device__ float g_x [ROWS*D_MODEL];
__device__ float g_xp[ROWS*2*D_INNER];
__device__ float g_dt[ROWS*D_INNER];
__device__ float g_Bm[ROWS*D_STATE];
__device__ float g_Cm[ROWS*D_STATE];
__device__ float g_y2[ROWS*D_MODEL];

// bf16 hi/lo split buffers
__device__ __nv_bfloat16 g_emb_h[VOCAB*D_MODEL], g_emb_l[VOCAB*D_MODEL];
__device__ __nv_bfloat16 g_Win_h[NL*2*D_INNER*D_MODEL], g_Win_l[NL*2*D_INNER*D_MODEL];
__device__ __nv_bfloat16 g_Wdt_h[NL*D_INNER*D_MODEL],   g_Wdt_l[NL*D_INNER*D_MODEL];
__device__ __nv_bfloat16 g_Wout_h[NL*D_MODEL*D_INNER],  g_Wout_l[NL*D_MODEL*D_INNER];
__device__ __nv_bfloat16 g_xh[ROWS*D_MODEL],  g_xl[ROWS*D_MODEL];
__device__ __nv_bfloat16 g_sgh[ROWS*D_INNER], g_sgl[ROWS*D_INNER];
__device__ __nv_bfloat16 g_xnh[ROWS*D_MODEL], g_xnl[ROWS*D_MODEL];

__device__ __forceinline__ void split2(float v, __nv_bfloat16& h, __nv_bfloat16& l) {
    h = __float2bfloat16(v);
    l = __float2bfloat16(v - __bfloat162float(h));
}

// ---------------- fp32 -> (hi,lo) bf16 split ----------------
__global__ void split_kernel(const float* __restrict__ w,
                             __nv_bfloat16* __restrict__ h,
                             __nv_bfloat16* __restrict__ l, int n)
{
    int i = blockIdx.x * 256 + threadIdx.x;
    if (i >= n) return;
    split2(w[i], h[i], l[i]);
}

// ---------------- embedding gather (+ split) ----------------
__global__ void embed_kernel(const int* __restrict__ ids,
                             const float* __restrict__ emb,
                             float* __restrict__ x,
                             __nv_bfloat16* __restrict__ xh,
                             __nv_bfloat16* __restrict__ xl)
{
    int idx = blockIdx.x * 256 + threadIdx.x;
    if (idx >= ROWS*D_MODEL) return;
    int r = idx / D_MODEL, c = idx - r*D_MODEL;
    float v = emb[(size_t)ids[r]*D_MODEL + c];
    x[idx] = v;
    split2(v, xh[idx], xl[idx]);
}

// ================= bf16x3 tensor-core GEMM (mma.sync HMMA) =================
// C[M,N] = A[M,K] * B[N,K]^T  where A ~= Ah+Al, B ~= Bh+Bl (bf16 hi/lo).
// Block tile 128x128, BK=32, 8 warps (2x4), warp tile 64x32, mma m16n8k16.
// 3-stage cp.async pipeline; pass-major MMA issue (16 independent accumulators
// between reuses of the same acc -> HMMA pipe issues at rate, not latency).

__device__ __forceinline__ void cp16(uint32_t s, const void* g) {
    asm volatile("cp.async.cg.shared.global [%0], [%1], 16;" :: "r"(s), "l"(g));
}
__device__ __forceinline__ void cp_commit() {
    asm volatile("cp.async.commit_group;");
}
template<int N> __device__ __forceinline__ void cp_wait() {
    asm volatile("cp.async.wait_group %0;" :: "n"(N));
}
__device__ __forceinline__ void ldm_x4(uint32_t (&r)[4], uint32_t addr) {
    asm volatile("ldmatrix.sync.aligned.m8n8.x4.shared.b16 {%0,%1,%2,%3}, [%4];"
        : "=r"(r[0]), "=r"(r[1]), "=r"(r[2]), "=r"(r[3]) : "r"(addr));
}
__device__ __forceinline__ void mma_bf16(float (&c)[4], const uint32_t (&a)[4],
                                         const uint32_t* b) {
    asm volatile(
        "mma.sync.aligned.m16n8k16.row.col.f32.bf16.bf16.f32 "
        "{%0,%1,%2,%3}, {%4,%5,%6,%7}, {%8,%9}, {%0,%1,%2,%3};"
        : "+f"(c[0]), "+f"(c[1]), "+f"(c[2]), "+f"(c[3])
        : "r"(a[0]), "r"(a[1]), "r"(a[2]), "r"(a[3]), "r"(b[0]), "r"(b[1]));
}

#define GPITCH 40                       // bf16 elems per smem row (32 data + 8 pad)
#define GTILE_B (128*GPITCH*2)          // bytes per tile (10240)
#define GSTAGE_B (4*GTILE_B)            // 4 tiles per stage (Ah,Al,Bh,Bl)
#define GSTAGES 3
#define GSMEM_B (GSTAGES*GSTAGE_B)      // 122880 bytes

__global__ __launch_bounds__(256, 1) void gemm_bf16x3(
    const __nv_bfloat16* __restrict__ Ah, const __nv_bfloat16* __restrict__ Al,
    const __nv_bfloat16* __restrict__ Bh, const __nv_bfloat16* __restrict__ Bl,
    float* __restrict__ C, int M, int N, int K)
{
    extern __shared__ __nv_bfloat16 sm[];
    int tid = threadIdx.x, lane = tid & 31, warp = tid >> 5;
    int wm = warp >> 2, wn = warp & 3;               // 2 x 4 warp grid
    int bm = blockIdx.y * 128, bn = blockIdx.x * 128;
    uint32_t sb = (uint32_t)__cvta_generic_to_shared(sm);

    float acc[4][4][4];
    #pragma unroll
    for (int i = 0; i < 4; ++i)
        #pragma unroll
        for (int j = 0; j < 4; ++j)
            #pragma unroll
            for (int k = 0; k < 4; ++k) acc[i][j][k] = 0.f;

    auto issue = [&](int stg, int k0) {
        uint32_t base = sb + stg * GSTAGE_B;
        #pragma unroll
        for (int i = 0; i < 2; ++i) {
            int chunk = tid + i * 256;               // 0..511
            int row = chunk >> 2, c16 = chunk & 3;   // 128 rows x 4 chunks of 16B
            uint32_t so = (uint32_t)(row * GPITCH + c16 * 8) * 2;
            size_t ga = (size_t)(bm + row) * K + k0 + c16 * 8;
            size_t gb = (size_t)(bn + row) * K + k0 + c16 * 8;
            cp16(base + so,              Ah + ga);
            cp16(base +   GTILE_B + so,  Al + ga);
            cp16(base + 2*GTILE_B + so,  Bh + gb);
            cp16(base + 3*GTILE_B + so,  Bl + gb);
        }
    };

    int nit = K / 32;
    issue(0, 0);
    cp_commit();
    if (nit > 1) { issue(1, 32); cp_commit(); }

    // per-lane ldmatrix address components (rows within tile, cols in elems)
    int a_r = wm * 64 + (lane & 7) + ((lane >> 3) & 1) * 8;
    int a_c = (lane >> 4) * 8;
    int b_r = wn * 32 + (lane & 7) + ((lane >> 4) & 1) * 8;
    int b_c = ((lane >> 3) & 1) * 8;

    for (int it = 0; it < nit; ++it) {
        // wait until stage it%3 is resident
        if (it + 1 < nit) cp_wait<1>(); else cp_wait<0>();
        __syncthreads();   // also: all warps finished compute(it-1) here

        // prefetch stage it+2 (overwrites stage (it-1)%3, safe after the sync)
        if (it + 2 < nit) { issue((it + 2) % GSTAGES, (it + 2) * 32); cp_commit(); }

        uint32_t base = sb + (it % GSTAGES) * GSTAGE_B;
        #pragma unroll
        for (int ks = 0; ks < 2; ++ks) {
            uint32_t ah[4][4], al[4][4], bh[4][2], bl[4][2];
            #pragma unroll
            for (int mt = 0; mt < 4; ++mt) {
                uint32_t off = (uint32_t)((a_r + mt * 16) * GPITCH + a_c + ks * 16) * 2;
                ldm_x4(ah[mt], base + off);
                ldm_x4(al[mt], base + GTILE_B + off);
            }
            #pragma unroll
            for (int g = 0; g < 2; ++g) {
                uint32_t off = (uint32_t)((b_r + g * 16) * GPITCH + b_c + ks * 16) * 2;
                uint32_t t[4];
                ldm_x4(t, base + 2*GTILE_B + off);
                bh[g*2][0] = t[0]; bh[g*2][1] = t[1];
                bh[g*2+1][0] = t[2]; bh[g*2+1][1] = t[3];
                ldm_x4(t, base + 3*GTILE_B + off);
                bl[g*2][0] = t[0]; bl[g*2][1] = t[1];
                bl[g*2+1][0] = t[2]; bl[g*2+1][1] = t[3];
            }
            // pass-major: 16 independent MMAs per pass
            #pragma unroll
            for (int mt = 0; mt < 4; ++mt)
                #pragma unroll
                for (int nt = 0; nt < 4; ++nt)
                    mma_bf16(acc[mt][nt], ah[mt], bh[nt]);
            #pragma unroll
            for (int mt = 0; mt < 4; ++mt)
                #pragma unroll
                for (int nt = 0; nt < 4; ++nt)
                    mma_bf16(acc[mt][nt], ah[mt], bl[nt]);
            #pragma unroll
            for (int mt = 0; mt < 4; ++mt)
                #pragma unroll
                for (int nt = 0; nt < 4; ++nt)
                    mma_bf16(acc[mt][nt], al[mt], bh[nt]);
        }
    }

    // epilogue
    #pragma unroll
    for (int mt = 0; mt < 4; ++mt) {
        int r = bm + wm * 64 + mt * 16 + (lane >> 2);
        #pragma unroll
        for (int nt = 0; nt < 4; ++nt) {
            int c = bn + wn * 32 + nt * 8 + (lane & 3) * 2;
            *(float2*)&C[(size_t)r * N + c]       = make_float2(acc[mt][nt][0], acc[mt][nt][1]);
            *(float2*)&C[(size_t)(r + 8) * N + c] = make_float2(acc[mt][nt][2], acc[mt][nt][3]);
        }
    }
}

// ---------------- dt activation: softplus(dt + b_dt + dt_bias) clipped to [0,1]
__global__ void dt_act_kernel(float* __restrict__ dt,
                              const float* __restrict__ bd,
                              const float* __restrict__ dtb)
{
    int idx = blockIdx.x * 256 + threadIdx.x;
    if (idx >= ROWS*D_INNER) return;
    int d = idx % D_INNER;
    float v = dt[idx] + bd[d] + dtb[d];
    float sp = (v > 20.f) ? v : log1pf(expf(v));
    dt[idx] = fminf(fmaxf(sp, 0.f), 1.f);
}

// ---------------- B/C projection: N=16 each, fused (reuses x row from smem)
__global__ __launch_bounds__(256) void bc_kernel(
    const float* __restrict__ x, const float* __restrict__ WB,
    const float* __restrict__ WC, float* __restrict__ Bm, float* __restrict__ Cm)
{
    int r = blockIdx.x;
    __shared__ float xs[D_MODEL];
    __shared__ float part[32][9];
    int tid = threadIdx.x;
    for (int i = tid; i < D_MODEL; i += 256) xs[i] = x[(size_t)r*D_MODEL + i];
    __syncthreads();

    int o = tid & 31;
    int chunk = tid >> 5;
    const float* w = (o < 16) ? (WB + (size_t)o*D_MODEL)
                              : (WC + (size_t)(o-16)*D_MODEL);
    float s = 0.f;
    int k0 = chunk * 96;
    #pragma unroll 4
    for (int k = k0; k < k0 + 96; ++k) s = fmaf(xs[k], w[k], s);
    part[o][chunk] = s;
    __syncthreads();
    if (tid < 32) {
        float t = 0.f;
        #pragma unroll
        for (int c = 0; c < 8; ++c) t += part[tid][c];
        if (tid < 16) Bm[(size_t)r*16 + tid]      = t;
        else          Cm[(size_t)r*16 + (tid-16)] = t;
    }
}

// ---------------- SSM scan: 8 threads/channel, 2 states/thread, fused gate+split
__global__ __launch_bounds__(128) void scan_kernel(
    const float* __restrict__ xp, const float* __restrict__ dt,
    const float* __restrict__ Bm, const float* __restrict__ Cm,
    const float* __restrict__ A,  const float* __restrict__ Dp,
    __nv_bfloat16* __restrict__ outh, __nv_bfloat16* __restrict__ outl)
{
    const int TPC = 8;
    int lane_c = threadIdx.x & (TPC-1);
    int ch = blockIdx.x * (128/TPC) + (threadIdx.x >> 3);
    int b = ch / D_INNER, d = ch - b*D_INNER;
    int s0 = lane_c * 2;

    float a0 = A[(size_t)d*D_STATE + s0];
    float a1 = A[(size_t)d*D_STATE + s0 + 1];
    float Dd = Dp[d];
    float h0 = 0.f, h1 = 0.f;

    const int rowbase = b * SEQ;
    for (int t = 0; t < SEQ; ++t) {
        int r = rowbase + t;
        float u   = xp[(size_t)r*(2*D_INNER) + d];
        float dtc = dt[(size_t)r*D_INNER + d];
        float2 Bv = *(const float2*)&Bm[(size_t)r*D_STATE + s0];
        float2 Cv = *(const float2*)&Cm[(size_t)r*D_STATE + s0];

        float adt0 = (a0 * dtc) * 0.1f;
        float adt1 = (a1 * dtc) * 0.1f;
        float bu0  = (Bv.x * u) * 0.1f;
        float bu1  = (Bv.y * u) * 0.1f;
        h0 = h0 * (1.0f + adt0) + bu0;
        h1 = h1 * (1.0f + adt1) + bu1;

        float y = fmaf(h0, Cv.x, h1 * Cv.y);
        y += __shfl_xor_sync(0xffffffffu, y, 1);
        y += __shfl_xor_sync(0xffffffffu, y, 2);
        y += __shfl_xor_sync(0xffffffffu, y, 4);

        if (lane_c == 0) {
            float gin = xp[(size_t)r*(2*D_INNER) + D_INNER + d];
            float gate = 1.0f / (1.0f + expf(-gin));
            float val = (y + Dd * u) * gate;
            size_t idx = (size_t)r*D_INNER + d;
            split2(val, outh[idx], outl[idx]);
        }
    }
}

// ---------------- block reduce helper ----------------
__device__ __forceinline__ float block_sum_256(float v, float* red) {
    #pragma unroll
    for (int m = 16; m > 0; m >>= 1) v += __shfl_xor_sync(0xffffffffu, v, m);
    int w = threadIdx.x >> 5;
    if ((threadIdx.x & 31) == 0) red[w] = v;
    __syncthreads();
    float s = 0.f;
    if (threadIdx.x == 0) {
        #pragma unroll
        for (int i = 0; i < 8; ++i) s += red[i];
        red[0] = s;
    }
    __syncthreads();
    s = red[0];
    __syncthreads();
    return s;
}

// ---------------- x = x + LN(x + y2) * g + b, plus hi/lo split of new x
__global__ __launch_bounds__(256) void ln_residual_kernel(
    float* __restrict__ x, const float* __restrict__ y2,
    const float* __restrict__ g, const float* __restrict__ b,
    __nv_bfloat16* __restrict__ xh, __nv_bfloat16* __restrict__ xl)
{
    __shared__ float red[8];
    int r = blockIdx.x, tid = threadIdx.x;
    size_t base = (size_t)r * D_MODEL;
    float v[3], xo[3];
    #pragma unroll
    for (int i = 0; i < 3; ++i) {
        int c = i*256 + tid;
        xo[i] = x[base + c];
        v[i]  = xo[i] + y2[base + c];
    }
    float mu = block_sum_256(v[0]+v[1]+v[2], red) * (1.0f/D_MODEL);
    float q = 0.f;
    #pragma unroll
    for (int i = 0; i < 3; ++i) { float dv = v[i]-mu; q = fmaf(dv, dv, q); }
    float var = block_sum_256(q, red) * (1.0f/D_MODEL);
    float rstd = rsqrtf(var + LN_EPS);
    #pragma unroll
    for (int i = 0; i < 3; ++i) {
        int c = i*256 + tid;
        float nv = xo[i] + (v[i]-mu)*rstd*g[c] + b[c];
        x[base + c] = nv;
        split2(nv, xh[base + c], xl[base + c]);
    }
}

// ---------------- xn = LN(x) * fin_g + fin_b, written as hi/lo bf16
__global__ __launch_bounds__(256) void final_ln_kernel(
    const float* __restrict__ x,
    __nv_bfloat16* __restrict__ xnh, __nv_bfloat16* __restrict__ xnl,
    const float* __restrict__ g, const float* __restrict__ b)
{
    __shared__ float red[8];
    int r = blockIdx.x, tid = threadIdx.x;
    size_t base = (size_t)r * D_MODEL;
    float v[3];
    #pragma unroll
    for (int i = 0; i < 3; ++i) v[i] = x[base + i*256 + tid];
    float mu = block_sum_256(v[0]+v[1]+v[2], red) * (1.0f/D_MODEL);
    float q = 0.f;
    #pragma unroll
    for (int i = 0; i < 3; ++i) { float dv = v[i]-mu; q = fmaf(dv, dv, q); }
    float var = block_sum_256(q, red) * (1.0f/D_MODEL);
    float rstd = rsqrtf(var + LN_EPS);
    #pragma unroll
    for (int i = 0; i < 3; ++i) {
        int c = i*256 + tid;
        float nv = (v[i]-mu)*rstd*g[c] + b[c];
        split2(nv, xnh[base + c], xnl[base + c]);
    }
}

// ---------------- launch ----------------
extern "C" void kernel_launch(void* const* d_in, const int* in_sizes, int n_in,
                              void* d_out, int out_size)
{
    const int*   ids    = (const int*)  d_in[0];
    const float* emb    = (const float*)d_in[1];
    const float* W_in   = (const float*)d_in[2];
    const float* W_dt   = (const float*)d_in[3];
    const float* b_dt   = (const float*)d_in[4];
    const float* dt_b   = (const float*)d_in[5];
    const float* W_B    = (const float*)d_in[6];
    const float* W_C    = (const float*)d_in[7];
    const float* A      = (const float*)d_in[8];
    const float* Dp     = (const float*)d_in[9];
    const float* W_out  = (const float*)d_in[10];
    const float* ln_g   = (const float*)d_in[11];
    const float* ln_b   = (const float*)d_in[12];
    const float* fin_g  = (const float*)d_in[13];
    const float* fin_b  = (const float*)d_in[14];
    float* out = (float*)d_out;

    float *x, *xp, *dt, *Bm, *Cm, *y2;
    cudaGetSymbolAddress((void**)&x,  g_x);
    cudaGetSymbolAddress((void**)&xp, g_xp);
    cudaGetSymbolAddress((void**)&dt, g_dt);
    cudaGetSymbolAddress((void**)&Bm, g_Bm);
    cudaGetSymbolAddress((void**)&Cm, g_Cm);
    cudaGetSymbolAddress((void**)&y2, g_y2);

    __nv_bfloat16 *embh, *embl, *winh, *winl, *wdth, *wdtl, *wouth, *woutl;
    __nv_bfloat16 *xh, *xl, *sgh, *sgl, *xnh, *xnl;
    cudaGetSymbolAddress((void**)&embh, g_emb_h);  cudaGetSymbolAddress((void**)&embl, g_emb_l);
    cudaGetSymbolAddress((void**)&winh, g_Win_h);  cudaGetSymbolAddress((void**)&winl, g_Win_l);
    cudaGetSymbolAddress((void**)&wdth, g_Wdt_h);  cudaGetSymbolAddress((void**)&wdtl, g_Wdt_l);
    cudaGetSymbolAddress((void**)&wouth, g_Wout_h); cudaGetSymbolAddress((void**)&woutl, g_Wout_l);
    cudaGetSymbolAddress((void**)&xh, g_xh);   cudaGetSymbolAddress((void**)&xl, g_xl);
    cudaGetSymbolAddress((void**)&sgh, g_sgh); cudaGetSymbolAddress((void**)&sgl, g_sgl);
    cudaGetSymbolAddress((void**)&xnh, g_xnh); cudaGetSymbolAddress((void**)&xnl, g_xnl);

    cudaFuncSetAttribute(gemm_bf16x3, cudaFuncAttributeMaxDynamicSharedMemorySize, GSMEM_B);

    // split weights + embedding into bf16 hi/lo
    {
        int n;
        n = VOCAB*D_MODEL;            split_kernel<<<(n+255)/256,256>>>(emb,   embh, embl, n);
        n = NL*2*D_INNER*D_MODEL;     split_kernel<<<(n+255)/256,256>>>(W_in,  winh, winl, n);
        n = NL*D_INNER*D_MODEL;       split_kernel<<<(n+255)/256,256>>>(W_dt,  wdth, wdtl, n);
        n = NL*D_MODEL*D_INNER;       split_kernel<<<(n+255)/256,256>>>(W_out, wouth, woutl, n);
    }

    embed_kernel<<<(ROWS*D_MODEL + 255)/256, 256>>>(ids, emb, x, xh, xl);

    for (int l = 0; l < NL; ++l) {
        size_t oWin = (size_t)l * (2*D_INNER) * D_MODEL;
        size_t oWdt = (size_t)l * D_INNER * D_MODEL;
        size_t oWo  = (size_t)l * D_MODEL * D_INNER;
        const float* bd  = b_dt + (size_t)l * D_INNER;
        const float* dtb = dt_b + (size_t)l * D_INNER;
        const float* WBl = W_B  + (size_t)l * D_STATE * D_MODEL;
        const float* WCl = W_C  + (size_t)l * D_STATE * D_MODEL;
        const float* Al  = A    + (size_t)l * D_INNER * D_STATE;
        const float* Dl  = Dp   + (size_t)l * D_INNER;
        const float* lg  = ln_g + (size_t)l * D_MODEL;
        const float* lb  = ln_b + (size_t)l * D_MODEL;

        gemm_bf16x3<<<dim3((2*D_INNER)/128, ROWS/128), 256, GSMEM_B>>>(
            xh, xl, winh + oWin, winl + oWin, xp, ROWS, 2*D_INNER, D_MODEL);
        gemm_bf16x3<<<dim3(D_INNER/128, ROWS/128), 256, GSMEM_B>>>(
            xh, xl, wdth + oWdt, wdtl + oWdt, dt, ROWS, D_INNER, D_MODEL);
        dt_act_kernel<<<(ROWS*D_INNER + 255)/256, 256>>>(dt, bd, dtb);
        bc_kernel<<<ROWS, 256>>>(x, WBl, WCl, Bm, Cm);
        scan_kernel<<<(BATCH*D_INNER)/16, 128>>>(xp, dt, Bm, Cm, Al, Dl, sgh, sgl);
        gemm_bf16x3<<<dim3(D_MODEL/128, ROWS/128), 256, GSMEM_B>>>(
            sgh, sgl, wouth + oWo, woutl + oWo, y2, ROWS, D_MODEL, D_INNER);
        ln_residual_kernel<<<ROWS, 256>>>(x, y2, lg, lb, xh, xl);
    }

    final_ln_kernel<<<ROWS, 256>>>(x, xnh, xnl, fin_g, fin_b);
    gemm_bf16x3<<<dim3(VOCAB/128, ROWS/128), 256, GSMEM_B>>>(
        xnh, xnl, embh, embl, out, ROWS, VOCAB, D_MODEL);
}

// round 11
// speedup vs baseline: 1.5298x; 1.0751x over previous
#include <cuda_runtime.h>
#include <cuda_bf16.h>
#include <math.h>
#include <stdint.h>

#define D_MODEL 768
#define D_STATE 16
#define VOCAB   32000
#define D_INNER 1536
#define BATCH   2
#define SEQ     2048
#define ROWS    (BATCH*SEQ)     // 4096
#define LN_EPS  1e-5f
#define NL      2

// ---------------- packed tile layout ----------------
// 128x32 bf16 tiles, row pitch 40 (32 data + 8 pad) -> 5120 elems = 10240 B,
// stored contiguously tile-major: tile_id = (r/128)*(K/32) + (c/32).
#define PT 5120
__device__ __forceinline__ size_t pidx(int r, int c, int Kd) {
    return (size_t)((r >> 7) * (Kd >> 5) + (c >> 5)) * PT + (r & 127) * 40 + (c & 31);
}
#define EMB_P  30720000u   // 32000x768 packed
#define WIN_P  2949120u    // 3072x768 packed (per layer)
#define WDT_P  1474560u    // 1536x768 packed (per layer)
#define WOUT_P 1474560u    // 768x1536 packed (per layer)
#define X_P    3932160u    // 4096x768 packed
#define SG_P   7864320u    // 4096x1536 packed

// ---------------- scratch (static device globals; no allocation) ----------------
__device__ float g_x [ROWS*D_MODEL];
__device__ float g_xp[ROWS*2*D_INNER];
__device__ float g_dt[ROWS*D_INNER];
__device__ float g_Bm[ROWS*D_STATE];
__device__ float g_Cm[ROWS*D_STATE];
__device__ float g_y2[ROWS*D_MODEL];

__device__ __align__(1024) __nv_bfloat16 g_emb_h[EMB_P],  g_emb_l[EMB_P];
__device__ __align__(1024) __nv_bfloat16 g_Win_h[NL*WIN_P],  g_Win_l[NL*WIN_P];
__device__ __align__(1024) __nv_bfloat16 g_Wdt_h[NL*WDT_P],  g_Wdt_l[NL*WDT_P];
__device__ __align__(1024) __nv_bfloat16 g_Wout_h[NL*WOUT_P], g_Wout_l[NL*WOUT_P];
__device__ __align__(1024) __nv_bfloat16 g_xh[X_P],  g_xl[X_P];
__device__ __align__(1024) __nv_bfloat16 g_sgh[SG_P], g_sgl[SG_P];
__device__ __align__(1024) __nv_bfloat16 g_xnh[X_P], g_xnl[X_P];

__device__ __forceinline__ void split2(float v, __nv_bfloat16& h, __nv_bfloat16& l) {
    h = __float2bfloat16(v);
    l = __float2bfloat16(v - __bfloat162float(h));
}

// ---------------- fp32 -> packed (hi,lo) bf16 split ----------------
__global__ void split_pack_kernel(const float* __restrict__ w,
                                  __nv_bfloat16* __restrict__ h,
                                  __nv_bfloat16* __restrict__ l, int n, int Kd)
{
    int i = blockIdx.x * 256 + threadIdx.x;
    if (i >= n) return;
    int r = i / Kd, c = i - r*Kd;
    size_t p = pidx(r, c, Kd);
    split2(w[i], h[p], l[p]);
}

// ---------------- embedding gather (+ packed split) ----------------
__global__ void embed_kernel(const int* __restrict__ ids,
                             const float* __restrict__ emb,
                             float* __restrict__ x,
                             __nv_bfloat16* __restrict__ xh,
                             __nv_bfloat16* __restrict__ xl)
{
    int idx = blockIdx.x * 256 + threadIdx.x;
    if (idx >= ROWS*D_MODEL) return;
    int r = idx / D_MODEL, c = idx - r*D_MODEL;
    float v = emb[(size_t)ids[r]*D_MODEL + c];
    x[idx] = v;
    size_t p = pidx(r, c, D_MODEL);
    split2(v, xh[p], xl[p]);
}

// ================= bf16x3 tensor-core GEMM (mma.sync + bulk-copy loads) =====
// C[M,N] = A[M,K] * B[N,K]^T, A ~= Ah+Al, B ~= Bh+Bl, all operands in packed
// tile-major layout. One cp.async.bulk per 10KB tile (4/stage), 3-stage
// mbarrier pipeline. Inner MMA loop identical to the proven R4/R9 kernel.

__device__ __forceinline__ uint32_t s2u(const void* p) {
    return (uint32_t)__cvta_generic_to_shared(p);
}
__device__ __forceinline__ void mbar_init(uint32_t mb, uint32_t cnt) {
    asm volatile("mbarrier.init.shared.b64 [%0], %1;" :: "r"(mb), "r"(cnt) : "memory");
}
__device__ __forceinline__ void mbar_expect(uint32_t mb, uint32_t tx) {
    asm volatile("mbarrier.arrive.expect_tx.shared.b64 _, [%0], %1;"
                 :: "r"(mb), "r"(tx) : "memory");
}
__device__ __forceinline__ void mbar_wait(uint32_t mb, uint32_t ph) {
    asm volatile(
        "{\n\t.reg .pred P1;\n\t"
        "WAIT_%=:\n\t"
        "mbarrier.try_wait.parity.acquire.cta.shared::cta.b64 P1, [%0], %1, 0x989680;\n\t"
        "@P1 bra.uni DONE_%=;\n\t"
        "bra.uni WAIT_%=;\n\t"
        "DONE_%=:\n\t}"
        :: "r"(mb), "r"(ph) : "memory");
}
__device__ __forceinline__ void bulkcp(uint32_t dst, const void* src,
                                       uint32_t bytes, uint32_t mb) {
    asm volatile(
        "cp.async.bulk.shared::cluster.global.mbarrier::complete_tx::bytes "
        "[%0], [%1], %2, [%3];"
        :: "r"(dst), "l"(src), "r"(bytes), "r"(mb) : "memory");
}
__device__ __forceinline__ void ldm_x4(uint32_t (&r)[4], uint32_t addr) {
    asm volatile("ldmatrix.sync.aligned.m8n8.x4.shared.b16 {%0,%1,%2,%3}, [%4];"
        : "=r"(r[0]), "=r"(r[1]), "=r"(r[2]), "=r"(r[3]) : "r"(addr));
}
__device__ __forceinline__ void mma_bf16(float (&c)[4], const uint32_t (&a)[4],
                                         const uint32_t* b) {
    asm volatile(
        "mma.sync.aligned.m16n8k16.row.col.f32.bf16.bf16.f32 "
        "{%0,%1,%2,%3}, {%4,%5,%6,%7}, {%8,%9}, {%0,%1,%2,%3};"
        : "+f"(c[0]), "+f"(c[1]), "+f"(c[2]), "+f"(c[3])
        : "r"(a[0]), "r"(a[1]), "r"(a[2]), "r"(a[3]), "r"(b[0]), "r"(b[1]));
}

#define GPITCH 40
#define GTILE_B (128*GPITCH*2)          // 10240 B per tile
#define GSTAGE_B (4*GTILE_B)            // 40960 B per stage (Ah,Al,Bh,Bl)
#define GSTAGES 3
#define GSMEM_B (GSTAGES*GSTAGE_B)      // 122880 B

__global__ __launch_bounds__(256, 1) void gemm_bf16x3(
    const __nv_bfloat16* __restrict__ Ah, const __nv_bfloat16* __restrict__ Al,
    const __nv_bfloat16* __restrict__ Bh, const __nv_bfloat16* __restrict__ Bl,
    float* __restrict__ C, int M, int N, int K)
{
    extern __shared__ __nv_bfloat16 sm[];
    __shared__ __align__(8) uint64_t mbar[GSTAGES];
    int tid = threadIdx.x, lane = tid & 31, warp = tid >> 5;
    int wm = warp >> 2, wn = warp & 3;               // 2 x 4 warp grid
    int bm = blockIdx.y * 128, bn = blockIdx.x * 128;
    uint32_t sb  = s2u(sm);
    uint32_t mb0 = s2u(&mbar[0]);
    int ntk = K >> 5;
    size_t aT = (size_t)(bm >> 7) * ntk;   // A tile-row base
    size_t bT = (size_t)(bn >> 7) * ntk;   // B tile-row base

    if (tid == 0) {
        mbar_init(mb0, 1); mbar_init(mb0 + 8, 1); mbar_init(mb0 + 16, 1);
    }
    __syncthreads();

    auto issue = [&](int s, int kc) {
        uint32_t mb = mb0 + s*8;
        mbar_expect(mb, GSTAGE_B);
        uint32_t d = sb + s * GSTAGE_B;
        bulkcp(d,             Ah + (aT + kc)*PT, GTILE_B, mb);
        bulkcp(d +   GTILE_B, Al + (aT + kc)*PT, GTILE_B, mb);
        bulkcp(d + 2*GTILE_B, Bh + (bT + kc)*PT, GTILE_B, mb);
        bulkcp(d + 3*GTILE_B, Bl + (bT + kc)*PT, GTILE_B, mb);
    };

    int nit = K / 32;                      // >= 24 for all our shapes
    if (tid == 0) { issue(0, 0); issue(1, 1); issue(2, 2); }

    float acc[4][4][4];
    #pragma unroll
    for (int i = 0; i < 4; ++i)
        #pragma unroll
        for (int j = 0; j < 4; ++j)
            #pragma unroll
            for (int k = 0; k < 4; ++k) acc[i][j][k] = 0.f;

    // per-lane ldmatrix address components (rows within tile, cols in elems)
    int a_r = wm * 64 + (lane & 7) + ((lane >> 3) & 1) * 8;
    int a_c = (lane >> 4) * 8;
    int b_r = wn * 32 + (lane & 7) + ((lane >> 4) & 1) * 8;
    int b_c = ((lane >> 3) & 1) * 8;

    uint32_t ph[GSTAGES] = {0, 0, 0};

    for (int it = 0; it < nit; ++it) {
        int s = it % GSTAGES;
        mbar_wait(mb0 + s*8, ph[s]); ph[s] ^= 1;

        uint32_t base = sb + s * GSTAGE_B;
        #pragma unroll
        for (int ks = 0; ks < 2; ++ks) {
            uint32_t ah[4][4], al[4][4], bh[4][2], bl[4][2];
            #pragma unroll
            for (int mt = 0; mt < 4; ++mt) {
                uint32_t off = (uint32_t)((a_r + mt * 16) * GPITCH + a_c + ks * 16) * 2;
                ldm_x4(ah[mt], base + off);
                ldm_x4(al[mt], base + GTILE_B + off);
            }
            #pragma unroll
            for (int g = 0; g < 2; ++g) {
                uint32_t off = (uint32_t)((b_r + g * 16) * GPITCH + b_c + ks * 16) * 2;
                uint32_t t[4];
                ldm_x4(t, base + 2*GTILE_B + off);
                bh[g*2][0] = t[0]; bh[g*2][1] = t[1];
                bh[g*2+1][0] = t[2]; bh[g*2+1][1] = t[3];
                ldm_x4(t, base + 3*GTILE_B + off);
                bl[g*2][0] = t[0]; bl[g*2][1] = t[1];
                bl[g*2+1][0] = t[2]; bl[g*2+1][1] = t[3];
            }
            #pragma unroll
            for (int mt = 0; mt < 4; ++mt)
                #pragma unroll
                for (int nt = 0; nt < 4; ++nt)
                    mma_bf16(acc[mt][nt], ah[mt], bh[nt]);
            #pragma unroll
            for (int mt = 0; mt < 4; ++mt)
                #pragma unroll
                for (int nt = 0; nt < 4; ++nt)
                    mma_bf16(acc[mt][nt], ah[mt], bl[nt]);
            #pragma unroll
            for (int mt = 0; mt < 4; ++mt)
                #pragma unroll
                for (int nt = 0; nt < 4; ++nt)
                    mma_bf16(acc[mt][nt], al[mt], bh[nt]);
        }
        __syncthreads();                        // all warps done with stage s
        if (tid == 0 && it + 3 < nit) issue(s, it + 3);
    }

    // epilogue
    #pragma unroll
    for (int mt = 0; mt < 4; ++mt) {
        int r = bm + wm * 64 + mt * 16 + (lane >> 2);
        #pragma unroll
        for (int nt = 0; nt < 4; ++nt) {
            int c = bn + wn * 32 + nt * 8 + (lane & 3) * 2;
            *(float2*)&C[(size_t)r * N + c]       = make_float2(acc[mt][nt][0], acc[mt][nt][1]);
            *(float2*)&C[(size_t)(r + 8) * N + c] = make_float2(acc[mt][nt][2], acc[mt][nt][3]);
        }
    }
}

// ---------------- dt activation: softplus(dt + b_dt + dt_bias) clipped to [0,1]
__global__ void dt_act_kernel(float* __restrict__ dt,
                              const float* __restrict__ bd,
                              const float* __restrict__ dtb)
{
    int idx = blockIdx.x * 256 + threadIdx.x;
    if (idx >= ROWS*D_INNER) return;
    int d = idx % D_INNER;
    float v = dt[idx] + bd[d] + dtb[d];
    float sp = (v > 20.f) ? v : log1pf(expf(v));
    dt[idx] = fminf(fmaxf(sp, 0.f), 1.f);
}

// ---------------- B/C projection: N=16 each, fused (reuses x row from smem)
__global__ __launch_bounds__(256) void bc_kernel(
    const float* __restrict__ x, const float* __restrict__ WB,
    const float* __restrict__ WC, float* __restrict__ Bm, float* __restrict__ Cm)
{
    int r = blockIdx.x;
    __shared__ float xs[D_MODEL];
    __shared__ float part[32][9];
    int tid = threadIdx.x;
    for (int i = tid; i < D_MODEL; i += 256) xs[i] = x[(size_t)r*D_MODEL + i];
    __syncthreads();

    int o = tid & 31;
    int chunk = tid >> 5;
    const float* w = (o < 16) ? (WB + (size_t)o*D_MODEL)
                              : (WC + (size_t)(o-16)*D_MODEL);
    float s = 0.f;
    int k0 = chunk * 96;
    #pragma unroll 4
    for (int k = k0; k < k0 + 96; ++k) s = fmaf(xs[k], w[k], s);
    part[o][chunk] = s;
    __syncthreads();
    if (tid < 32) {
        float t = 0.f;
        #pragma unroll
        for (int c = 0; c < 8; ++c) t += part[tid][c];
        if (tid < 16) Bm[(size_t)r*16 + tid]      = t;
        else          Cm[(size_t)r*16 + (tid-16)] = t;
    }
}

// ---------------- SSM scan: 8 threads/channel, 2 states/thread, fused gate+pack
__global__ __launch_bounds__(128) void scan_kernel(
    const float* __restrict__ xp, const float* __restrict__ dt,
    const float* __restrict__ Bm, const float* __restrict__ Cm,
    const float* __restrict__ A,  const float* __restrict__ Dp,
    __nv_bfloat16* __restrict__ outh, __nv_bfloat16* __restrict__ outl)
{
    const int TPC = 8;
    int lane_c = threadIdx.x & (TPC-1);
    int ch = blockIdx.x * (128/TPC) + (threadIdx.x >> 3);
    int b = ch / D_INNER, d = ch - b*D_INNER;
    int s0 = lane_c * 2;

    float a0 = A[(size_t)d*D_STATE + s0];
    float a1 = A[(size_t)d*D_STATE + s0 + 1];
    float Dd = Dp[d];
    float h0 = 0.f, h1 = 0.f;

    const int rowbase = b * SEQ;
    for (int t = 0; t < SEQ; ++t) {
        int r = rowbase + t;
        float u   = xp[(size_t)r*(2*D_INNER) + d];
        float dtc = dt[(size_t)r*D_INNER + d];
        float2 Bv = *(const float2*)&Bm[(size_t)r*D_STATE + s0];
        float2 Cv = *(const float2*)&Cm[(size_t)r*D_STATE + s0];

        float adt0 = (a0 * dtc) * 0.1f;
        float adt1 = (a1 * dtc) * 0.1f;
        float bu0  = (Bv.x * u) * 0.1f;
        float bu1  = (Bv.y * u) * 0.1f;
        h0 = h0 * (1.0f + adt0) + bu0;
        h1 = h1 * (1.0f + adt1) + bu1;

        float y = fmaf(h0, Cv.x, h1 * Cv.y);
        y += __shfl_xor_sync(0xffffffffu, y, 1);
        y += __shfl_xor_sync(0xffffffffu, y, 2);
        y += __shfl_xor_sync(0xffffffffu, y, 4);

        if (lane_c == 0) {
            float gin = xp[(size_t)r*(2*D_INNER) + D_INNER + d];
            float gate = 1.0f / (1.0f + expf(-gin));
            float val = (y + Dd * u) * gate;
            size_t p = pidx(r, d, D_INNER);
            split2(val, outh[p], outl[p]);
        }
    }
}

// ---------------- block reduce helper ----------------
__device__ __forceinline__ float block_sum_256(float v, float* red) {
    #pragma unroll
    for (int m = 16; m > 0; m >>= 1) v += __shfl_xor_sync(0xffffffffu, v, m);
    int w = threadIdx.x >> 5;
    if ((threadIdx.x & 31) == 0) red[w] = v;
    __syncthreads();
    float s = 0.f;
    if (threadIdx.x == 0) {
        #pragma unroll
        for (int i = 0; i < 8; ++i) s += red[i];
        red[0] = s;
    }
    __syncthreads();
    s = red[0];
    __syncthreads();
    return s;
}

// ---------------- x = x + LN(x + y2) * g + b, plus packed hi/lo split of new x
__global__ __launch_bounds__(256) void ln_residual_kernel(
    float* __restrict__ x, const float* __restrict__ y2,
    const float* __restrict__ g, const float* __restrict__ b,
    __nv_bfloat16* __restrict__ xh, __nv_bfloat16* __restrict__ xl)
{
    __shared__ float red[8];
    int r = blockIdx.x, tid = threadIdx.x;
    size_t base = (size_t)r * D_MODEL;
    float v[3], xo[3];
    #pragma unroll
    for (int i = 0; i < 3; ++i) {
        int c = i*256 + tid;
        xo[i] = x[base + c];
        v[i]  = xo[i] + y2[base + c];
    }
    float mu = block_sum_256(v[0]+v[1]+v[2], red) * (1.0f/D_MODEL);
    float q = 0.f;
    #pragma unroll
    for (int i = 0; i < 3; ++i) { float dv = v[i]-mu; q = fmaf(dv, dv, q); }
    float var = block_sum_256(q, red) * (1.0f/D_MODEL);
    float rstd = rsqrtf(var + LN_EPS);
    #pragma unroll
    for (int i = 0; i < 3; ++i) {
        int c = i*256 + tid;
        float nv = xo[i] + (v[i]-mu)*rstd*g[c] + b[c];
        x[base + c] = nv;
        size_t p = pidx(r, c, D_MODEL);
        split2(nv, xh[p], xl[p]);
    }
}

// ---------------- xn = LN(x) * fin_g + fin_b, written packed hi/lo bf16
__global__ __launch_bounds__(256) void final_ln_kernel(
    const float* __restrict__ x,
    __nv_bfloat16* __restrict__ xnh, __nv_bfloat16* __restrict__ xnl,
    const float* __restrict__ g, const float* __restrict__ b)
{
    __shared__ float red[8];
    int r = blockIdx.x, tid = threadIdx.x;
    size_t base = (size_t)r * D_MODEL;
    float v[3];
    #pragma unroll
    for (int i = 0; i < 3; ++i) v[i] = x[base + i*256 + tid];
    float mu = block_sum_256(v[0]+v[1]+v[2], red) * (1.0f/D_MODEL);
    float q = 0.f;
    #pragma unroll
    for (int i = 0; i < 3; ++i) { float dv = v[i]-mu; q = fmaf(dv, dv, q); }
    float var = block_sum_256(q, red) * (1.0f/D_MODEL);
    float rstd = rsqrtf(var + LN_EPS);
    #pragma unroll
    for (int i = 0; i < 3; ++i) {
        int c = i*256 + tid;
        float nv = (v[i]-mu)*rstd*g[c] + b[c];
        size_t p = pidx(r, c, D_MODEL);
        split2(nv, xnh[p], xnl[p]);
    }
}

// ---------------- launch ----------------
extern "C" void kernel_launch(void* const* d_in, const int* in_sizes, int n_in,
                              void* d_out, int out_size)
{
    const int*   ids    = (const int*)  d_in[0];
    const float* emb    = (const float*)d_in[1];
    const float* W_in   = (const float*)d_in[2];
    const float* W_dt   = (const float*)d_in[3];
    const float* b_dt   = (const float*)d_in[4];
    const float* dt_b   = (const float*)d_in[5];
    const float* W_B    = (const float*)d_in[6];
    const float* W_C    = (const float*)d_in[7];
    const float* A      = (const float*)d_in[8];
    const float* Dp     = (const float*)d_in[9];
    const float* W_out  = (const float*)d_in[10];
    const float* ln_g   = (const float*)d_in[11];
    const float* ln_b   = (const float*)d_in[12];
    const float* fin_g  = (const float*)d_in[13];
    const float* fin_b  = (const float*)d_in[14];
    float* out = (float*)d_out;

    float *x, *xp, *dt, *Bm, *Cm, *y2;
    cudaGetSymbolAddress((void**)&x,  g_x);
    cudaGetSymbolAddress((void**)&xp, g_xp);
    cudaGetSymbolAddress((void**)&dt, g_dt);
    cudaGetSymbolAddress((void**)&Bm, g_Bm);
    cudaGetSymbolAddress((void**)&Cm, g_Cm);
    cudaGetSymbolAddress((void**)&y2, g_y2);

    __nv_bfloat16 *embh, *embl, *winh, *winl, *wdth, *wdtl, *wouth, *woutl;
    __nv_bfloat16 *xh, *xl, *sgh, *sgl, *xnh, *xnl;
    cudaGetSymbolAddress((void**)&embh, g_emb_h);  cudaGetSymbolAddress((void**)&embl, g_emb_l);
    cudaGetSymbolAddress((void**)&winh, g_Win_h);  cudaGetSymbolAddress((void**)&winl, g_Win_l);
    cudaGetSymbolAddress((void**)&wdth, g_Wdt_h);  cudaGetSymbolAddress((void**)&wdtl, g_Wdt_l);
    cudaGetSymbolAddress((void**)&wouth, g_Wout_h); cudaGetSymbolAddress((void**)&woutl, g_Wout_l);
    cudaGetSymbolAddress((void**)&xh, g_xh);   cudaGetSymbolAddress((void**)&xl, g_xl);
    cudaGetSymbolAddress((void**)&sgh, g_sgh); cudaGetSymbolAddress((void**)&sgl, g_sgl);
    cudaGetSymbolAddress((void**)&xnh, g_xnh); cudaGetSymbolAddress((void**)&xnl, g_xnl);

    cudaFuncSetAttribute(gemm_bf16x3, cudaFuncAttributeMaxDynamicSharedMemorySize, GSMEM_B);

    // split + pack weights and embedding into tile-major bf16 hi/lo
    {
        int n = VOCAB*D_MODEL;
        split_pack_kernel<<<(n+255)/256,256>>>(emb, embh, embl, n, D_MODEL);
        for (int l = 0; l < NL; ++l) {
            n = 2*D_INNER*D_MODEL;
            split_pack_kernel<<<(n+255)/256,256>>>(W_in + (size_t)l*n,
                winh + (size_t)l*WIN_P, winl + (size_t)l*WIN_P, n, D_MODEL);
            n = D_INNER*D_MODEL;
            split_pack_kernel<<<(n+255)/256,256>>>(W_dt + (size_t)l*n,
                wdth + (size_t)l*WDT_P, wdtl + (size_t)l*WDT_P, n, D_MODEL);
            n = D_MODEL*D_INNER;
            split_pack_kernel<<<(n+255)/256,256>>>(W_out + (size_t)l*n,
                wouth + (size_t)l*WOUT_P, woutl + (size_t)l*WOUT_P, n, D_INNER);
        }
    }

    embed_kernel<<<(ROWS*D_MODEL + 255)/256, 256>>>(ids, emb, x, xh, xl);

    for (int l = 0; l < NL; ++l) {
        const float* bd  = b_dt + (size_t)l * D_INNER;
        const float* dtb = dt_b + (size_t)l * D_INNER;
        const float* WBl = W_B  + (size_t)l * D_STATE * D_MODEL;
        const float* WCl = W_C  + (size_t)l * D_STATE * D_MODEL;
        const float* Al  = A    + (size_t)l * D_INNER * D_STATE;
        const float* Dl  = Dp   + (size_t)l * D_INNER;
        const float* lg  = ln_g + (size_t)l * D_MODEL;
        const float* lb  = ln_b + (size_t)l * D_MODEL;

        gemm_bf16x3<<<dim3((2*D_INNER)/128, ROWS/128), 256, GSMEM_B>>>(
            xh, xl, winh + (size_t)l*WIN_P, winl + (size_t)l*WIN_P,
            xp, ROWS, 2*D_INNER, D_MODEL);
        gemm_bf16x3<<<dim3(D_INNER/128, ROWS/128), 256, GSMEM_B>>>(
            xh, xl, wdth + (size_t)l*WDT_P, wdtl + (size_t)l*WDT_P,
            dt, ROWS, D_INNER, D_MODEL);
        dt_act_kernel<<<(ROWS*D_INNER + 255)/256, 256>>>(dt, bd, dtb);
        bc_kernel<<<ROWS, 256>>>(x, WBl, WCl, Bm, Cm);
        scan_kernel<<<(BATCH*D_INNER)/16, 128>>>(xp, dt, Bm, Cm, Al, Dl, sgh, sgl);
        gemm_bf16x3<<<dim3(D_MODEL/128, ROWS/128), 256, GSMEM_B>>>(
            sgh, sgl, wouth + (size_t)l*WOUT_P, woutl + (size_t)l*WOUT_P,
            y2, ROWS, D_MODEL, D_INNER);
        ln_residual_kernel<<<ROWS, 256>>>(x, y2, lg, lb, xh, xl);
    }

    final_ln_kernel<<<ROWS, 256>>>(x, xnh, xnl, fin_g, fin_b);
    gemm_bf16x3<<<dim3(VOCAB/128, ROWS/128), 256, GSMEM_B>>>(
        xnh, xnl, embh, embl, out, ROWS, VOCAB, D_MODEL);
}

// round 15
// speedup vs baseline: 1.6593x; 1.0846x over previous
#include <cuda_runtime.h>
#include <cuda_fp16.h>
#include <math.h>
#include <stdint.h>

#define D_MODEL 768
#define D_STATE 16
#define VOCAB   32000
#define D_INNER 1536
#define BATCH   2
#define SEQ     2048
#define ROWS    (BATCH*SEQ)     // 4096
#define LN_EPS  1e-5f
#define NL      2

// ---------------- packed tile layout ----------------
// 128x32 fp16 tiles, row pitch 40 (32 data + 8 pad) -> 5120 elems = 10240 B,
// stored contiguously tile-major: tile_id = (r/128)*(K/32) + (c/32).
#define PT 5120
__device__ __forceinline__ size_t pidx(int r, int c, int Kd) {
    return (size_t)((r >> 7) * (Kd >> 5) + (c >> 5)) * PT + (r & 127) * 40 + (c & 31);
}
#define EMB_P  30720000u   // 32000x768 packed
#define WIN_P  2949120u    // 3072x768 packed (per layer)
#define WDT_P  1474560u    // 1536x768 packed (per layer)
#define WOUT_P 1474560u    // 768x1536 packed (per layer)
#define X_P    3932160u    // 4096x768 packed
#define SG_P   7864320u    // 4096x1536 packed

// ---------------- scratch (static device globals; no allocation) ----------------
__device__ float g_x [ROWS*D_MODEL];
__device__ float g_xp[ROWS*2*D_INNER];
__device__ float g_dt[ROWS*D_INNER];
__device__ float g_Bm[ROWS*D_STATE];
__device__ float g_Cm[ROWS*D_STATE];
__device__ float g_y2[ROWS*D_MODEL];

// B-side (weights/emb): hi only. A-side (activations): hi + lo.
__device__ __align__(1024) __half g_emb_h[EMB_P];
__device__ __align__(1024) __half g_Win_h[NL*WIN_P];
__device__ __align__(1024) __half g_Wdt_h[NL*WDT_P];
__device__ __align__(1024) __half g_Wout_h[NL*WOUT_P];
__device__ __align__(1024) __half g_xh[X_P],  g_xl[X_P];
__device__ __align__(1024) __half g_sgh[SG_P], g_sgl[SG_P];
__device__ __align__(1024) __half g_xnh[X_P], g_xnl[X_P];

__device__ __forceinline__ void split2(float v, __half& h, __half& l) {
    h = __float2half_rn(v);
    l = __float2half_rn(v - __half2float(h));
}

// ---------------- fp32 -> packed fp16 hi (weights / emb, B side) -------------
__global__ void pack_hi_kernel(const float* __restrict__ w,
                               __half* __restrict__ h, int n, int Kd)
{
    int i = blockIdx.x * 256 + threadIdx.x;
    if (i >= n) return;
    int r = i / Kd, c = i - r*Kd;
    h[pidx(r, c, Kd)] = __float2half_rn(w[i]);
}

// ---------------- embedding gather (+ packed hi/lo split) ----------------
__global__ void embed_kernel(const int* __restrict__ ids,
                             const float* __restrict__ emb,
                             float* __restrict__ x,
                             __half* __restrict__ xh,
                             __half* __restrict__ xl)
{
    int idx = blockIdx.x * 256 + threadIdx.x;
    if (idx >= ROWS*D_MODEL) return;
    int r = idx / D_MODEL, c = idx - r*D_MODEL;
    float v = emb[(size_t)ids[r]*D_MODEL + c];
    x[idx] = v;
    size_t p = pidx(r, c, D_MODEL);
    split2(v, xh[p], xl[p]);
}

// ================= fp16x2 tensor-core GEMM (mma.sync + bulk-copy loads) =====
// C[M,N] = A[M,K] * B[N,K]^T with A = Ah+Al (exact fp16 split), B ~= Bh.
// Error = A*Bl ~ 2^-12/sqrt(3) relative. 2 MMA passes per tile (was 3).
// Packed tile-major operands, one cp.async.bulk per 10KB tile (3/stage),
// 4-stage mbarrier pipeline. Inner fragment/MMA layout identical to R4/R11.

__device__ __forceinline__ uint32_t s2u(const void* p) {
    return (uint32_t)__cvta_generic_to_shared(p);
}
__device__ __forceinline__ void mbar_init(uint32_t mb, uint32_t cnt) {
    asm volatile("mbarrier.init.shared.b64 [%0], %1;" :: "r"(mb), "r"(cnt) : "memory");
}
__device__ __forceinline__ void mbar_expect(uint32_t mb, uint32_t tx) {
    asm volatile("mbarrier.arrive.expect_tx.shared.b64 _, [%0], %1;"
                 :: "r"(mb), "r"(tx) : "memory");
}
__device__ __forceinline__ void mbar_wait(uint32_t mb, uint32_t ph) {
    asm volatile(
        "{\n\t.reg .pred P1;\n\t"
        "WAIT_%=:\n\t"
        "mbarrier.try_wait.parity.acquire.cta.shared::cta.b64 P1, [%0], %1, 0x989680;\n\t"
        "@P1 bra.uni DONE_%=;\n\t"
        "bra.uni WAIT_%=;\n\t"
        "DONE_%=:\n\t}"
        :: "r"(mb), "r"(ph) : "memory");
}
__device__ __forceinline__ void bulkcp(uint32_t dst, const void* src,
                                       uint32_t bytes, uint32_t mb) {
    asm volatile(
        "cp.async.bulk.shared::cluster.global.mbarrier::complete_tx::bytes "
        "[%0], [%1], %2, [%3];"
        :: "r"(dst), "l"(src), "r"(bytes), "r"(mb) : "memory");
}
__device__ __forceinline__ void ldm_x4(uint32_t (&r)[4], uint32_t addr) {
    asm volatile("ldmatrix.sync.aligned.m8n8.x4.shared.b16 {%0,%1,%2,%3}, [%4];"
        : "=r"(r[0]), "=r"(r[1]), "=r"(r[2]), "=r"(r[3]) : "r"(addr));
}
__device__ __forceinline__ void mma_fp16(float (&c)[4], const uint32_t (&a)[4],
                                         const uint32_t* b) {
    asm volatile(
        "mma.sync.aligned.m16n8k16.row.col.f32.f16.f16.f32 "
        "{%0,%1,%2,%3}, {%4,%5,%6,%7}, {%8,%9}, {%0,%1,%2,%3};"
        : "+f"(c[0]), "+f"(c[1]), "+f"(c[2]), "+f"(c[3])
        : "r"(a[0]), "r"(a[1]), "r"(a[2]), "r"(a[3]), "r"(b[0]), "r"(b[1]));
}

#define GPITCH 40
#define GTILE_B (128*GPITCH*2)          // 10240 B per tile
#define GSTAGE_B (3*GTILE_B)            // 30720 B per stage (Ah,Al,Bh)
#define GSTAGES 4
#define GSMEM_B (GSTAGES*GSTAGE_B)      // 122880 B

__global__ __launch_bounds__(256, 1) void gemm_fp16x2(
    const __half* __restrict__ Ah, const __half* __restrict__ Al,
    const __half* __restrict__ Bh,
    float* __restrict__ C, int M, int N, int K)
{
    extern __shared__ __half sm[];
    __shared__ __align__(8) uint64_t mbar[GSTAGES];
    int tid = threadIdx.x, lane = tid & 31, warp = tid >> 5;
    int wm = warp >> 2, wn = warp & 3;               // 2 x 4 warp grid
    int bm = blockIdx.y * 128, bn = blockIdx.x * 128;
    uint32_t sb  = s2u(sm);
    uint32_t mb0 = s2u(&mbar[0]);
    int ntk = K >> 5;
    size_t aT = (size_t)(bm >> 7) * ntk;   // A tile-row base
    size_t bT = (size_t)(bn >> 7) * ntk;   // B tile-row base

    if (tid == 0) {
        #pragma unroll
        for (int s = 0; s < GSTAGES; ++s) mbar_init(mb0 + s*8, 1);
    }
    __syncthreads();

    auto issue = [&](int s, int kc) {
        uint32_t mb = mb0 + s*8;
        mbar_expect(mb, GSTAGE_B);
        uint32_t d = sb + s * GSTAGE_B;
        bulkcp(d,             Ah + (aT + kc)*PT, GTILE_B, mb);
        bulkcp(d +   GTILE_B, Al + (aT + kc)*PT, GTILE_B, mb);
        bulkcp(d + 2*GTILE_B, Bh + (bT + kc)*PT, GTILE_B, mb);
    };

    int nit = K / 32;                      // 24 or 48 here (>= GSTAGES)
    if (tid == 0) {
        issue(0, 0); issue(1, 1); issue(2, 2); issue(3, 3);
    }

    float acc[4][4][4];
    #pragma unroll
    for (int i = 0; i < 4; ++i)
        #pragma unroll
        for (int j = 0; j < 4; ++j)
            #pragma unroll
            for (int k = 0; k < 4; ++k) acc[i][j][k] = 0.f;

    // per-lane ldmatrix address components (rows within tile, cols in elems)
    int a_r = wm * 64 + (lane & 7) + ((lane >> 3) & 1) * 8;
    int a_c = (lane >> 4) * 8;
    int b_r = wn * 32 + (lane & 7) + ((lane >> 4) & 1) * 8;
    int b_c = ((lane >> 3) & 1) * 8;

    uint32_t ph[GSTAGES] = {0, 0, 0, 0};

    for (int it = 0; it < nit; ++it) {
        int s = it % GSTAGES;
        mbar_wait(mb0 + s*8, ph[s]); ph[s] ^= 1;

        uint32_t base = sb + s * GSTAGE_B;
        #pragma unroll
        for (int ks = 0; ks < 2; ++ks) {
            uint32_t ah[4][4], al[4][4], bh[4][2];
            #pragma unroll
            for (int mt = 0; mt < 4; ++mt) {
                uint32_t off = (uint32_t)((a_r + mt * 16) * GPITCH + a_c + ks * 16) * 2;
                ldm_x4(ah[mt], base + off);
                ldm_x4(al[mt], base + GTILE_B + off);
            }
            #pragma unroll
            for (int g = 0; g < 2; ++g) {
                uint32_t off = (uint32_t)((b_r + g * 16) * GPITCH + b_c + ks * 16) * 2;
                uint32_t t[4];
                ldm_x4(t, base + 2*GTILE_B + off);
                bh[g*2][0] = t[0]; bh[g*2][1] = t[1];
                bh[g*2+1][0] = t[2]; bh[g*2+1][1] = t[3];
            }
            #pragma unroll
            for (int mt = 0; mt < 4; ++mt)
                #pragma unroll
                for (int nt = 0; nt < 4; ++nt)
                    mma_fp16(acc[mt][nt], ah[mt], bh[nt]);
            #pragma unroll
            for (int mt = 0; mt < 4; ++mt)
                #pragma unroll
                for (int nt = 0; nt < 4; ++nt)
                    mma_fp16(acc[mt][nt], al[mt], bh[nt]);
        }
        __syncthreads();                        // all warps done with stage s
        if (tid == 0 && it + GSTAGES < nit) issue(s, it + GSTAGES);
    }

    // epilogue
    #pragma unroll
    for (int mt = 0; mt < 4; ++mt) {
        int r = bm + wm * 64 + mt * 16 + (lane >> 2);
        #pragma unroll
        for (int nt = 0; nt < 4; ++nt) {
            int c = bn + wn * 32 + nt * 8 + (lane & 3) * 2;
            *(float2*)&C[(size_t)r * N + c]       = make_float2(acc[mt][nt][0], acc[mt][nt][1]);
            *(float2*)&C[(size_t)(r + 8) * N + c] = make_float2(acc[mt][nt][2], acc[mt][nt][3]);
        }
    }
}

// ---------------- dt activation: softplus(dt + b_dt + dt_bias) clipped to [0,1]
__global__ void dt_act_kernel(float* __restrict__ dt,
                              const float* __restrict__ bd,
                              const float* __restrict__ dtb)
{
    int idx = blockIdx.x * 256 + threadIdx.x;
    if (idx >= ROWS*D_INNER) return;
    int d = idx % D_INNER;
    float v = dt[idx] + bd[d] + dtb[d];
    float sp = (v > 20.f) ? v : log1pf(expf(v));
    dt[idx] = fminf(fmaxf(sp, 0.f), 1.f);
}

// ---------------- B/C projection: N=16 each, fused (reuses x row from smem)
__global__ __launch_bounds__(256) void bc_kernel(
    const float* __restrict__ x, const float* __restrict__ WB,
    const float* __restrict__ WC, float* __restrict__ Bm, float* __restrict__ Cm)
{
    int r = blockIdx.x;
    __shared__ float xs[D_MODEL];
    __shared__ float part[32][9];
    int tid = threadIdx.x;
    for (int i = tid; i < D_MODEL; i += 256) xs[i] = x[(size_t)r*D_MODEL + i];
    __syncthreads();

    int o = tid & 31;
    int chunk = tid >> 5;
    const float* w = (o < 16) ? (WB + (size_t)o*D_MODEL)
                              : (WC + (size_t)(o-16)*D_MODEL);
    float s = 0.f;
    int k0 = chunk * 96;
    #pragma unroll 4
    for (int k = k0; k < k0 + 96; ++k) s = fmaf(xs[k], w[k], s);
    part[o][chunk] = s;
    __syncthreads();
    if (tid < 32) {
        float t = 0.f;
        #pragma unroll
        for (int c = 0; c < 8; ++c) t += part[tid][c];
        if (tid < 16) Bm[(size_t)r*16 + tid]      = t;
        else          Cm[(size_t)r*16 + (tid-16)] = t;
    }
}

// ---------------- SSM scan: 8 threads/channel, 2 states/thread, fused gate+pack
__global__ __launch_bounds__(128) void scan_kernel(
    const float* __restrict__ xp, const float* __restrict__ dt,
    const float* __restrict__ Bm, const float* __restrict__ Cm,
    const float* __restrict__ A,  const float* __restrict__ Dp,
    __half* __restrict__ outh, __half* __restrict__ outl)
{
    const int TPC = 8;
    int lane_c = threadIdx.x & (TPC-1);
    int ch = blockIdx.x * (128/TPC) + (threadIdx.x >> 3);
    int b = ch / D_INNER, d = ch - b*D_INNER;
    int s0 = lane_c * 2;

    float a0 = A[(size_t)d*D_STATE + s0];
    float a1 = A[(size_t)d*D_STATE + s0 + 1];
    float Dd = Dp[d];
    float h0 = 0.f, h1 = 0.f;

    const int rowbase = b * SEQ;
    for (int t = 0; t < SEQ; ++t) {
        int r = rowbase + t;
        float u   = xp[(size_t)r*(2*D_INNER) + d];
        float dtc = dt[(size_t)r*D_INNER + d];
        float2 Bv = *(const float2*)&Bm[(size_t)r*D_STATE + s0];
        float2 Cv = *(const float2*)&Cm[(size_t)r*D_STATE + s0];

        float adt0 = (a0 * dtc) * 0.1f;
        float adt1 = (a1 * dtc) * 0.1f;
        float bu0  = (Bv.x * u) * 0.1f;
        float bu1  = (Bv.y * u) * 0.1f;
        h0 = h0 * (1.0f + adt0) + bu0;
        h1 = h1 * (1.0f + adt1) + bu1;

        float y = fmaf(h0, Cv.x, h1 * Cv.y);
        y += __shfl_xor_sync(0xffffffffu, y, 1);
        y += __shfl_xor_sync(0xffffffffu, y, 2);
        y += __shfl_xor_sync(0xffffffffu, y, 4);

        if (lane_c == 0) {
            float gin = xp[(size_t)r*(2*D_INNER) + D_INNER + d];
            float gate = 1.0f / (1.0f + expf(-gin));
            float val = (y + Dd * u) * gate;
            size_t p = pidx(r, d, D_INNER);
            split2(val, outh[p], outl[p]);
        }
    }
}

// ---------------- block reduce helper ----------------
__device__ __forceinline__ float block_sum_256(float v, float* red) {
    #pragma unroll
    for (int m = 16; m > 0; m >>= 1) v += __shfl_xor_sync(0xffffffffu, v, m);
    int w = threadIdx.x >> 5;
    if ((threadIdx.x & 31) == 0) red[w] = v;
    __syncthreads();
    float s = 0.f;
    if (threadIdx.x == 0) {
        #pragma unroll
        for (int i = 0; i < 8; ++i) s += red[i];
        red[0] = s;
    }
    __syncthreads();
    s = red[0];
    __syncthreads();
    return s;
}

// ---------------- x = x + LN(x + y2) * g + b, plus packed hi/lo split of new x
__global__ __launch_bounds__(256) void ln_residual_kernel(
    float* __restrict__ x, const float* __restrict__ y2,
    const float* __restrict__ g, const float* __restrict__ b,
    __half* __restrict__ xh, __half* __restrict__ xl)
{
    __shared__ float red[8];
    int r = blockIdx.x, tid = threadIdx.x;
    size_t base = (size_t)r * D_MODEL;
    float v[3], xo[3];
    #pragma unroll
    for (int i = 0; i < 3; ++i) {
        int c = i*256 + tid;
        xo[i] = x[base + c];
        v[i]  = xo[i] + y2[base + c];
    }
    float mu = block_sum_256(v[0]+v[1]+v[2], red) * (1.0f/D_MODEL);
    float q = 0.f;
    #pragma unroll
    for (int i = 0; i < 3; ++i) { float dv = v[i]-mu; q = fmaf(dv, dv, q); }
    float var = block_sum_256(q, red) * (1.0f/D_MODEL);
    float rstd = rsqrtf(var + LN_EPS);
    #pragma unroll
    for (int i = 0; i < 3; ++i) {
        int c = i*256 + tid;
        float nv = xo[i] + (v[i]-mu)*rstd*g[c] + b[c];
        x[base + c] = nv;
        size_t p = pidx(r, c, D_MODEL);
        split2(nv, xh[p], xl[p]);
    }
}

// ---------------- xn = LN(x) * fin_g + fin_b, written packed hi/lo fp16
__global__ __launch_bounds__(256) void final_ln_kernel(
    const float* __restrict__ x,
    __half* __restrict__ xnh, __half* __restrict__ xnl,
    const float* __restrict__ g, const float* __restrict__ b)
{
    __shared__ float red[8];
    int r = blockIdx.x, tid = threadIdx.x;
    size_t base = (size_t)r * D_MODEL;
    float v[3];
    #pragma unroll
    for (int i = 0; i < 3; ++i) v[i] = x[base + i*256 + tid];
    float mu = block_sum_256(v[0]+v[1]+v[2], red) * (1.0f/D_MODEL);
    float q = 0.f;
    #pragma unroll
    for (int i = 0; i < 3; ++i) { float dv = v[i]-mu; q = fmaf(dv, dv, q); }
    float var = block_sum_256(q, red) * (1.0f/D_MODEL);
    float rstd = rsqrtf(var + LN_EPS);
    #pragma unroll
    for (int i = 0; i < 3; ++i) {
        int c = i*256 + tid;
        float nv = (v[i]-mu)*rstd*g[c] + b[c];
        size_t p = pidx(r, c, D_MODEL);
        split2(nv, xnh[p], xnl[p]);
    }
}

// ---------------- launch ----------------
extern "C" void kernel_launch(void* const* d_in, const int* in_sizes, int n_in,
                              void* d_out, int out_size)
{
    const int*   ids    = (const int*)  d_in[0];
    const float* emb    = (const float*)d_in[1];
    const float* W_in   = (const float*)d_in[2];
    const float* W_dt   = (const float*)d_in[3];
    const float* b_dt   = (const float*)d_in[4];
    const float* dt_b   = (const float*)d_in[5];
    const float* W_B    = (const float*)d_in[6];
    const float* W_C    = (const float*)d_in[7];
    const float* A      = (const float*)d_in[8];
    const float* Dp     = (const float*)d_in[9];
    const float* W_out  = (const float*)d_in[10];
    const float* ln_g   = (const float*)d_in[11];
    const float* ln_b   = (const float*)d_in[12];
    const float* fin_g  = (const float*)d_in[13];
    const float* fin_b  = (const float*)d_in[14];
    float* out = (float*)d_out;

    float *x, *xp, *dt, *Bm, *Cm, *y2;
    cudaGetSymbolAddress((void**)&x,  g_x);
    cudaGetSymbolAddress((void**)&xp, g_xp);
    cudaGetSymbolAddress((void**)&dt, g_dt);
    cudaGetSymbolAddress((void**)&Bm, g_Bm);
    cudaGetSymbolAddress((void**)&Cm, g_Cm);
    cudaGetSymbolAddress((void**)&y2, g_y2);

    __half *embh, *winh, *wdth, *wouth;
    __half *xh, *xl, *sgh, *sgl, *xnh, *xnl;
    cudaGetSymbolAddress((void**)&embh, g_emb_h);
    cudaGetSymbolAddress((void**)&winh, g_Win_h);
    cudaGetSymbolAddress((void**)&wdth, g_Wdt_h);
    cudaGetSymbolAddress((void**)&wouth, g_Wout_h);
    cudaGetSymbolAddress((void**)&xh, g_xh);   cudaGetSymbolAddress((void**)&xl, g_xl);
    cudaGetSymbolAddress((void**)&sgh, g_sgh); cudaGetSymbolAddress((void**)&sgl, g_sgl);
    cudaGetSymbolAddress((void**)&xnh, g_xnh); cudaGetSymbolAddress((void**)&xnl, g_xnl);

    cudaFuncSetAttribute(gemm_fp16x2, cudaFuncAttributeMaxDynamicSharedMemorySize, GSMEM_B);

    // pack weights + embedding (hi-only, B side)
    {
        int n = VOCAB*D_MODEL;
        pack_hi_kernel<<<(n+255)/256,256>>>(emb, embh, n, D_MODEL);
        for (int l = 0; l < NL; ++l) {
            n = 2*D_INNER*D_MODEL;
            pack_hi_kernel<<<(n+255)/256,256>>>(W_in + (size_t)l*n,
                winh + (size_t)l*WIN_P, n, D_MODEL);
            n = D_INNER*D_MODEL;
            pack_hi_kernel<<<(n+255)/256,256>>>(W_dt + (size_t)l*n,
                wdth + (size_t)l*WDT_P, n, D_MODEL);
            n = D_MODEL*D_INNER;
            pack_hi_kernel<<<(n+255)/256,256>>>(W_out + (size_t)l*n,
                wouth + (size_t)l*WOUT_P, n, D_INNER);
        }
    }

    embed_kernel<<<(ROWS*D_MODEL + 255)/256, 256>>>(ids, emb, x, xh, xl);

    for (int l = 0; l < NL; ++l) {
        const float* bd  = b_dt + (size_t)l * D_INNER;
        const float* dtb = dt_b + (size_t)l * D_INNER;
        const float* WBl = W_B  + (size_t)l * D_STATE * D_MODEL;
        const float* WCl = W_C  + (size_t)l * D_STATE * D_MODEL;
        const float* Al  = A    + (size_t)l * D_INNER * D_STATE;
        const float* Dl  = Dp   + (size_t)l * D_INNER;
        const float* lg  = ln_g + (size_t)l * D_MODEL;
        const float* lb  = ln_b + (size_t)l * D_MODEL;

        gemm_fp16x2<<<dim3((2*D_INNER)/128, ROWS/128), 256, GSMEM_B>>>(
            xh, xl, winh + (size_t)l*WIN_P, xp, ROWS, 2*D_INNER, D_MODEL);
        gemm_fp16x2<<<dim3(D_INNER/128, ROWS/128), 256, GSMEM_B>>>(
            xh, xl, wdth + (size_t)l*WDT_P, dt, ROWS, D_INNER, D_MODEL);
        dt_act_kernel<<<(ROWS*D_INNER + 255)/256, 256>>>(dt, bd, dtb);
        bc_kernel<<<ROWS, 256>>>(x, WBl, WCl, Bm, Cm);
        scan_kernel<<<(BATCH*D_INNER)/16, 128>>>(xp, dt, Bm, Cm, Al, Dl, sgh, sgl);
        gemm_fp16x2<<<dim3(D_MODEL/128, ROWS/128), 256, GSMEM_B>>>(
            sgh, sgl, wouth + (size_t)l*WOUT_P, y2, ROWS, D_MODEL, D_INNER);
        ln_residual_kernel<<<ROWS, 256>>>(x, y2, lg, lb, xh, xl);
    }

    final_ln_kernel<<<ROWS, 256>>>(x, xnh, xnl, fin_g, fin_b);
    gemm_fp16x2<<<dim3(VOCAB/128, ROWS/128), 256, GSMEM_B>>>(
        xnh, xnl, embh, out, ROWS, VOCAB, D_MODEL);
}